// round 2
// baseline (speedup 1.0000x reference)
#include <cuda_runtime.h>
#include <cstdint>
#include <math.h>

// Problem dims
#define LSEQ   1024
#define G3     768        // 3*OUT_H
#define HID    256        // OUT_H
#define DEH    512
#define NTAGS  6
#define CLN    8          // cluster size per cell
#define START_TAG 4

// ---------------- scratch (device globals; no allocation) ----------------
__device__ float g_GiF[LSEQ * G3];
__device__ float g_GiB[LSEQ * G3];
__device__ float g_O0 [LSEQ * 512];
__device__ float g_H1 [LSEQ * 512];
__device__ float g_EO [LSEQ * 512];
__device__ float g_tab_val[NTAGS];
__device__ int   g_tab_next[NTAGS];

// ---------------- helpers ----------------
__device__ __forceinline__ float wred_sum(float v) {
#pragma unroll
    for (int o = 16; o; o >>= 1) v += __shfl_xor_sync(0xffffffffu, v, o);
    return v;
}
__device__ __forceinline__ float wred_max(float v) {
#pragma unroll
    for (int o = 16; o; o >>= 1) v = fmaxf(v, __shfl_xor_sync(0xffffffffu, v, o));
    return v;
}
__device__ __forceinline__ float sigm(float x) { return 1.0f / (1.0f + expf(-x)); }
__device__ __forceinline__ void cluster_sync_asm() {
    asm volatile("barrier.cluster.arrive.aligned;" ::: "memory");
    asm volatile("barrier.cluster.wait.aligned;" ::: "memory");
}

// ---------------- GEMM: Gi[t][n] = sum_k A(t,k)*W[n][k] + bih[n] ----------------
// mode 0: A(t,k) = emb[x[t]*256 + k], K=256.  mode 1: A = g_O0, K=512.
// blockIdx.z selects cell (f/b). Tile: BM=64, BN=64, BK=32, 256 threads, 4x4/thread.
__global__ void gemm_gi_kernel(const int* __restrict__ x,
                               const float* __restrict__ emb,
                               int mode, int K,
                               const float* __restrict__ Wf, const float* __restrict__ Wb,
                               const float* __restrict__ bf, const float* __restrict__ bb,
                               float* __restrict__ GiF_out, float* __restrict__ GiB_out)
{
    const float* W   = blockIdx.z ? Wb : Wf;
    const float* bih = blockIdx.z ? bb : bf;
    float* Gi        = blockIdx.z ? GiB_out : GiF_out;

    __shared__ float As[32][68];
    __shared__ float Bs[32][68];

    int tid = threadIdx.x;
    int ty = tid >> 4, tx = tid & 15;
    int m0 = blockIdx.x * 64, n0 = blockIdx.y * 64;

    int lr = tid >> 2;            // 0..63
    int kc = (tid & 3) * 8;       // 0,8,16,24

    const float* arow;
    if (mode == 0) arow = emb + (size_t)x[m0 + lr] * 256;
    else           arow = g_O0 + (size_t)(m0 + lr) * K;
    const float* brow = W + (size_t)(n0 + lr) * K;

    float acc[4][4] = {};

    for (int k0 = 0; k0 < K; k0 += 32) {
        float4 a0 = *(const float4*)(arow + k0 + kc);
        float4 a1 = *(const float4*)(arow + k0 + kc + 4);
        float4 b0 = *(const float4*)(brow + k0 + kc);
        float4 b1 = *(const float4*)(brow + k0 + kc + 4);
        __syncthreads();
        As[kc+0][lr]=a0.x; As[kc+1][lr]=a0.y; As[kc+2][lr]=a0.z; As[kc+3][lr]=a0.w;
        As[kc+4][lr]=a1.x; As[kc+5][lr]=a1.y; As[kc+6][lr]=a1.z; As[kc+7][lr]=a1.w;
        Bs[kc+0][lr]=b0.x; Bs[kc+1][lr]=b0.y; Bs[kc+2][lr]=b0.z; Bs[kc+3][lr]=b0.w;
        Bs[kc+4][lr]=b1.x; Bs[kc+5][lr]=b1.y; Bs[kc+6][lr]=b1.z; Bs[kc+7][lr]=b1.w;
        __syncthreads();
#pragma unroll
        for (int kk = 0; kk < 32; kk++) {
            float4 av = *(const float4*)&As[kk][ty * 4];
            float4 bv = *(const float4*)&Bs[kk][tx * 4];
            float a4[4] = {av.x, av.y, av.z, av.w};
            float b4[4] = {bv.x, bv.y, bv.z, bv.w};
#pragma unroll
            for (int i = 0; i < 4; i++)
#pragma unroll
                for (int j = 0; j < 4; j++)
                    acc[i][j] += a4[i] * b4[j];
        }
    }
#pragma unroll
    for (int i = 0; i < 4; i++) {
        int m = m0 + ty * 4 + i;
#pragma unroll
        for (int j = 0; j < 4; j++) {
            int n = n0 + tx * 4 + j;
            Gi[(size_t)m * G3 + n] = acc[i][j] + bih[n];
        }
    }
}

// ---------------- cluster GRU recurrence (one layer, both cells) ----------------
// Grid = 16 CTAs = 2 clusters of 8 (cell 0 = fwd, cell 1 = bwd).
// CTA rank owns hidden j in [rank*32, rank*32+32). 384 threads: q=tid/96, rowLocal=tid%96.
// Each thread holds 64 Whh weights in registers.
__global__ void __cluster_dims__(CLN, 1, 1) recur_kernel(
    const float* __restrict__ WhhF, const float* __restrict__ WhhB,
    const float* __restrict__ bhhF, const float* __restrict__ bhhB,
    const float* __restrict__ hinit, int slotBase, int layer)
{
    int cell = blockIdx.x / CLN;
    unsigned rank;
    asm("mov.u32 %0, %%cluster_ctarank;" : "=r"(rank));

    const float* Gi  = cell ? g_GiB : g_GiF;
    const float* Whh = cell ? WhhB : WhhF;
    const float* bhh = cell ? bhhB : bhhF;
    float* Out       = layer ? g_H1 : g_O0;

    __shared__ float hbuf[2][256];
    __shared__ float red[4 * 96];
    __shared__ float gis[96];
    __shared__ float bhhs[96];

    int tid = threadIdx.x;
    int q  = tid / 96;
    int rl = tid % 96;
    int g  = rl >> 5, jj = rl & 31;
    int rowGlobal = g * 256 + (int)rank * 32 + jj;

    // preload Whh slice into registers
    float4 w4[16];
    const float* wp = Whh + (size_t)rowGlobal * 256 + q * 64;
#pragma unroll
    for (int i = 0; i < 16; i++) w4[i] = *(const float4*)(wp + i * 4);

    if (tid < 256) hbuf[0][tid] = hinit[(slotBase + cell) * 256 + tid];
    if (tid < 96)  bhhs[tid] = bhh[rowGlobal];
    __syncthreads();
    cluster_sync_asm();

    for (int t = 0; t < LSEQ; t++) {
        int cur = t & 1, nxt = cur ^ 1;
        if (tid < 96) gis[tid] = Gi[(size_t)t * G3 + rowGlobal];

        const float* hc = hbuf[cur] + q * 64;
        float ax = 0.f, ay = 0.f, az = 0.f, aw = 0.f;
#pragma unroll
        for (int i = 0; i < 16; i++) {
            float4 hv = *(const float4*)(hc + i * 4);
            ax += w4[i].x * hv.x; ay += w4[i].y * hv.y;
            az += w4[i].z * hv.z; aw += w4[i].w * hv.w;
        }
        red[q * 96 + rl] = (ax + ay) + (az + aw);
        __syncthreads();

        if (tid < 32) {
            float ghr = red[tid]      + red[96 + tid]      + red[192 + tid]      + red[288 + tid]      + bhhs[tid];
            float ghz = red[32 + tid] + red[96 + 32 + tid] + red[192 + 32 + tid] + red[288 + 32 + tid] + bhhs[32 + tid];
            float ghn = red[64 + tid] + red[96 + 64 + tid] + red[192 + 64 + tid] + red[288 + 64 + tid] + bhhs[64 + tid];
            float r = sigm(gis[tid] + ghr);
            float z = sigm(gis[32 + tid] + ghz);
            float n = tanhf(gis[64 + tid] + r * ghn);
            float hp = hbuf[cur][rank * 32 + tid];
            float hn_ = (1.0f - z) * n + z * hp;
            Out[(size_t)t * 512 + cell * 256 + rank * 32 + tid] = hn_;

            uint32_t la = (uint32_t)__cvta_generic_to_shared(&hbuf[nxt][rank * 32 + tid]);
#pragma unroll
            for (int d = 0; d < CLN; d++) {
                uint32_t ra;
                asm("mapa.shared::cluster.u32 %0, %1, %2;" : "=r"(ra) : "r"(la), "r"(d));
                asm volatile("st.shared::cluster.f32 [%0], %1;" :: "r"(ra), "f"(hn_) : "memory");
            }
        }
        cluster_sync_asm();
    }
}

// ---------------- per-row log_softmax over 512: H1 -> EO ----------------
__global__ void logsoftmax_kernel()
{
    int t = blockIdx.x, tid = threadIdx.x;   // 128 threads
    __shared__ float sred[4], sred2[4];
    float4 v = *(const float4*)(g_H1 + (size_t)t * 512 + tid * 4);
    float m = fmaxf(fmaxf(v.x, v.y), fmaxf(v.z, v.w));
    m = wred_max(m);
    if ((tid & 31) == 0) sred[tid >> 5] = m;
    __syncthreads();
    m = fmaxf(fmaxf(sred[0], sred[1]), fmaxf(sred[2], sred[3]));
    float s = expf(v.x - m) + expf(v.y - m) + expf(v.z - m) + expf(v.w - m);
    s = wred_sum(s);
    if ((tid & 31) == 0) sred2[tid >> 5] = s;
    __syncthreads();
    s = sred2[0] + sred2[1] + sred2[2] + sred2[3];
    float lg = m + logf(s);
    float4 o4 = {v.x - lg, v.y - lg, v.z - lg, v.w - lg};
    *(float4*)(g_EO + (size_t)t * 512 + tid * 4) = o4;
}

// ---------------- decoder table: 6 CTAs (one per input tag), 1024 threads ----------------
__global__ void decoder_kernel(const float* __restrict__ de_emb,
                               const float* __restrict__ attn_W, const float* __restrict__ attn_b,
                               const float* __restrict__ comb_W, const float* __restrict__ comb_b,
                               const float* __restrict__ de_Wih, const float* __restrict__ de_Whh,
                               const float* __restrict__ de_bih, const float* __restrict__ de_bhh,
                               const float* __restrict__ h2t_W,  const float* __restrict__ h2t_b)
{
    int tag = blockIdx.x;
    __shared__ float s_cat[1024], s_dh[512], s_aw[1024], s_tmp[1024];
    __shared__ float s_o[512], s_gi[1536], s_gh[1536], s_hn[512];
    __shared__ float s_logit[8], s_red[32], s_bc[2];

    int tid = threadIdx.x;
    int lane = tid & 31, w = tid >> 5;

    if (tid < 512) {
        s_cat[tid] = de_emb[tag * 512 + tid];
    } else {
        int j = tid - 512;
        float v = (j < 256) ? g_O0[(size_t)(LSEQ - 1) * 512 + j]
                            : g_H1[(size_t)(LSEQ - 1) * 512 + j];
        s_dh[j] = v;
        s_cat[tid] = v;
    }
    __syncthreads();

    // attn logits: 32 warps x 32 rows, dot(1024)
    for (int r = 0; r < 32; r++) {
        int m = w * 32 + r;
        const float4* wr = (const float4*)(attn_W + (size_t)m * 1024);
        float acc = 0.f;
#pragma unroll
        for (int i = 0; i < 8; i++) {
            float4 wv = wr[lane + i * 32];
            float4 cv = *(const float4*)&s_cat[(lane + i * 32) * 4];
            acc += wv.x * cv.x + wv.y * cv.y + wv.z * cv.z + wv.w * cv.w;
        }
        acc = wred_sum(acc);
        if (lane == 0) s_aw[m] = acc + attn_b[m];
    }
    __syncthreads();

    // softmax over 1024
    {
        float v = s_aw[tid];
        float m = wred_max(v);
        if (lane == 0) s_red[w] = m;
        __syncthreads();
        if (w == 0) {
            float mm = s_red[lane];
            mm = wred_max(mm);
            if (lane == 0) s_bc[0] = mm;
        }
        __syncthreads();
        float M = s_bc[0];
        float ex = expf(v - M);
        float s = wred_sum(ex);
        if (lane == 0) s_red[w] = s;
        __syncthreads();
        if (w == 0) {
            float ss = s_red[lane];
            ss = wred_sum(ss);
            if (lane == 0) s_bc[1] = ss;
        }
        __syncthreads();
        s_aw[tid] = ex / s_bc[1];
    }
    __syncthreads();

    // ctx = aw @ EO : split t-range in halves across the 1024 threads
    {
        int j = tid & 511, half = tid >> 9;
        float acc = 0.f;
        int t0 = half * 512;
#pragma unroll 8
        for (int t2 = t0; t2 < t0 + 512; t2++)
            acc += s_aw[t2] * g_EO[(size_t)t2 * 512 + j];
        s_tmp[tid] = acc;
    }
    __syncthreads();
    if (tid < 512) s_cat[512 + tid] = s_tmp[tid] + s_tmp[tid + 512];
    __syncthreads();

    // o = relu(comb_W @ [e, ctx] + b): 32 warps x 16 rows, dot(1024)
    for (int r = 0; r < 16; r++) {
        int m = w * 16 + r;
        const float4* wr = (const float4*)(comb_W + (size_t)m * 1024);
        float acc = 0.f;
#pragma unroll
        for (int i = 0; i < 8; i++) {
            float4 wv = wr[lane + i * 32];
            float4 cv = *(const float4*)&s_cat[(lane + i * 32) * 4];
            acc += wv.x * cv.x + wv.y * cv.y + wv.z * cv.z + wv.w * cv.w;
        }
        acc = wred_sum(acc);
        if (lane == 0) s_o[m] = fmaxf(acc + comb_b[m], 0.f);
    }
    __syncthreads();

    // GRU gate pre-activations: 3072 warp-rows of dot(512)
    for (int idx = w; idx < 3072; idx += 32) {
        const float* Wrow;
        const float* xin;
        int m;
        if (idx < 1536) { m = idx;        Wrow = de_Wih + (size_t)m * 512; xin = s_o;  }
        else            { m = idx - 1536; Wrow = de_Whh + (size_t)m * 512; xin = s_dh; }
        float acc = 0.f;
#pragma unroll
        for (int i = 0; i < 4; i++) {
            float4 wv = *(const float4*)(Wrow + (size_t)(lane + i * 32) * 4);
            float4 cv = *(const float4*)&xin[(lane + i * 32) * 4];
            acc += wv.x * cv.x + wv.y * cv.y + wv.z * cv.z + wv.w * cv.w;
        }
        acc = wred_sum(acc);
        if (lane == 0) {
            if (idx < 1536) s_gi[m] = acc + de_bih[m];
            else            s_gh[m] = acc + de_bhh[m];
        }
    }
    __syncthreads();

    if (tid < 512) {
        float r = sigm(s_gi[tid] + s_gh[tid]);
        float z = sigm(s_gi[512 + tid] + s_gh[512 + tid]);
        float n = tanhf(s_gi[1024 + tid] + r * s_gh[1024 + tid]);
        s_hn[tid] = (1.0f - z) * n + z * s_dh[tid];
    }
    __syncthreads();

    if (w < NTAGS) {
        const float4* wr = (const float4*)(h2t_W + (size_t)w * 512);
        float acc = 0.f;
#pragma unroll
        for (int i = 0; i < 4; i++) {
            float4 wv = wr[lane + i * 32];
            float4 cv = *(const float4*)&s_hn[(lane + i * 32) * 4];
            acc += wv.x * cv.x + wv.y * cv.y + wv.z * cv.z + wv.w * cv.w;
        }
        acc = wred_sum(acc);
        if (lane == 0) s_logit[w] = acc + h2t_b[w];
    }
    __syncthreads();

    if (tid == 0) {
        float mx = s_logit[0];
        int am = 0;
        for (int i = 1; i < NTAGS; i++)
            if (s_logit[i] > mx) { mx = s_logit[i]; am = i; }
        float se = 0.f;
        for (int i = 0; i < NTAGS; i++) se += expf(s_logit[i] - mx);
        g_tab_val[tag]  = s_logit[0] - mx - logf(se);
        g_tab_next[tag] = am;
    }
}

// ---------------- final: simulate 6-state chain via cycle detection + fill output ----------------
__global__ void final_kernel(const float* __restrict__ h2t_W,
                             const float* __restrict__ h2t_b,
                             float* __restrict__ out)
{
    __shared__ float s_rowsum[NTAGS], s_val[NTAGS], s_b[NTAGS];
    __shared__ int   s_next[NTAGS], s_seq[8];
    __shared__ int   s_tail, s_per;

    int tid = threadIdx.x, lane = tid & 31, w = tid >> 5;
    if (w < NTAGS) {
        float acc = 0.f;
        for (int i = lane; i < 512; i += 32) acc += h2t_W[(size_t)w * 512 + i];
        acc = wred_sum(acc);
        if (lane == 0) s_rowsum[w] = acc;
    }
    if (tid < NTAGS) {
        s_val[tid]  = g_tab_val[tid];
        s_next[tid] = g_tab_next[tid];
        s_b[tid]    = h2t_b[tid];
    }
    __syncthreads();

    if (tid == 0) {
        int s = START_TAG;
        int seq[8];
        for (int i = 0; i < 8; i++) { seq[i] = s; s_seq[i] = s; s = s_next[s]; }
        int tail = 0, per = 1;
        bool found = false;
        for (int k = 1; k < 8 && !found; k++)
            for (int j = 0; j < k; j++)
                if (seq[k] == seq[j]) { tail = j; per = k - j; found = true; break; }
        s_tail = tail; s_per = per;
    }
    __syncthreads();

    int i = tid;  // 1024 threads == LSEQ rows
    int st = (i < s_tail) ? s_seq[i] : s_seq[s_tail + (i - s_tail) % s_per];
    float c = s_val[st];
#pragma unroll
    for (int t = 0; t < NTAGS; t++)
        out[(size_t)i * NTAGS + t] = c * s_rowsum[t] + s_b[t];
}

// ---------------- host ----------------
extern "C" void kernel_launch(void* const* d_in, const int* in_sizes, int n_in,
                              void* d_out, int out_size)
{
    const int*   x       = (const int*)  d_in[0];
    const float* emb     = (const float*)d_in[1];
    const float* Wih0f   = (const float*)d_in[2];
    const float* Whh0f   = (const float*)d_in[3];
    const float* bih0f   = (const float*)d_in[4];
    const float* bhh0f   = (const float*)d_in[5];
    const float* Wih0b   = (const float*)d_in[6];
    const float* Whh0b   = (const float*)d_in[7];
    const float* bih0b   = (const float*)d_in[8];
    const float* bhh0b   = (const float*)d_in[9];
    const float* Wih1f   = (const float*)d_in[10];
    const float* Whh1f   = (const float*)d_in[11];
    const float* bih1f   = (const float*)d_in[12];
    const float* bhh1f   = (const float*)d_in[13];
    const float* Wih1b   = (const float*)d_in[14];
    const float* Whh1b   = (const float*)d_in[15];
    const float* bih1b   = (const float*)d_in[16];
    const float* bhh1b   = (const float*)d_in[17];
    const float* ehid0   = (const float*)d_in[18];
    const float* de_emb  = (const float*)d_in[19];
    const float* attn_W  = (const float*)d_in[20];
    const float* attn_b  = (const float*)d_in[21];
    const float* comb_W  = (const float*)d_in[22];
    const float* comb_b  = (const float*)d_in[23];
    const float* de_Wih  = (const float*)d_in[24];
    const float* de_Whh  = (const float*)d_in[25];
    const float* de_bih  = (const float*)d_in[26];
    const float* de_bhh  = (const float*)d_in[27];
    const float* h2t_W   = (const float*)d_in[28];
    const float* h2t_b   = (const float*)d_in[29];
    float* out = (float*)d_out;

    float *GiF_p = nullptr, *GiB_p = nullptr;
    cudaGetSymbolAddress((void**)&GiF_p, g_GiF);
    cudaGetSymbolAddress((void**)&GiB_p, g_GiB);

    // Layer 0 input GEMM: Gi = Wih0 @ emb[x] + bih0  (K=256)
    gemm_gi_kernel<<<dim3(16, 12, 2), 256>>>(x, emb, 0, 256,
                                             Wih0f, Wih0b, bih0f, bih0b, GiF_p, GiB_p);
    // Layer 0 recurrence -> g_O0
    recur_kernel<<<16, 384>>>(Whh0f, Whh0b, bhh0f, bhh0b, ehid0, 0, 0);
    // Layer 1 input GEMM: Gi = Wih1 @ O0 + bih1  (K=512)
    gemm_gi_kernel<<<dim3(16, 12, 2), 256>>>(nullptr, nullptr, 1, 512,
                                             Wih1f, Wih1b, bih1f, bih1b, GiF_p, GiB_p);
    // Layer 1 recurrence -> g_H1
    recur_kernel<<<16, 384>>>(Whh1f, Whh1b, bhh1f, bhh1b, ehid0, 2, 1);
    // eoutputs = log_softmax(H1 rows)
    logsoftmax_kernel<<<LSEQ, 128>>>();
    // 6-entry decoder FSM table
    decoder_kernel<<<NTAGS, 1024>>>(de_emb, attn_W, attn_b, comb_W, comb_b,
                                    de_Wih, de_Whh, de_bih, de_bhh, h2t_W, h2t_b);
    // chain + output
    final_kernel<<<1, 1024>>>(h2t_W, h2t_b, out);

    (void)in_sizes; (void)n_in; (void)out_size;
}

// round 3
// speedup vs baseline: 1.3496x; 1.3496x over previous
#include <cuda_runtime.h>
#include <cstdint>
#include <math.h>

// Problem dims
#define LSEQ   1024
#define G3     768        // 3*OUT_H
#define HID    256        // OUT_H
#define DEH    512
#define NTAGS  6
#define CLN    8          // cluster size per cell
#define START_TAG 4

// ---------------- scratch (device globals; no allocation) ----------------
__device__ float g_GiF[LSEQ * G3];
__device__ float g_GiB[LSEQ * G3];
__device__ float g_O0 [LSEQ * 512];
__device__ float g_H1 [LSEQ * 512];
__device__ float g_EO [LSEQ * 512];
__device__ float g_tab_val[NTAGS];
__device__ int   g_tab_next[NTAGS];

// ---------------- helpers ----------------
__device__ __forceinline__ float wred_sum(float v) {
#pragma unroll
    for (int o = 16; o; o >>= 1) v += __shfl_xor_sync(0xffffffffu, v, o);
    return v;
}
__device__ __forceinline__ float wred_max(float v) {
#pragma unroll
    for (int o = 16; o; o >>= 1) v = fmaxf(v, __shfl_xor_sync(0xffffffffu, v, o));
    return v;
}
__device__ __forceinline__ float sigm(float x) { return 1.0f / (1.0f + expf(-x)); }
// fast versions for the recurrent critical path (err ~1e-6; contraction keeps it bounded)
__device__ __forceinline__ float fsigm(float x) { return __fdividef(1.0f, 1.0f + __expf(-x)); }
__device__ __forceinline__ float ftanh(float x) {
    // tanh(x) = 1 - 2/(exp(2x)+1); __expf saturates correctly at +-inf
    return 1.0f - __fdividef(2.0f, __expf(2.0f * x) + 1.0f);
}
__device__ __forceinline__ void cluster_sync_asm() {
    asm volatile("barrier.cluster.arrive.aligned;" ::: "memory");
    asm volatile("barrier.cluster.wait.aligned;" ::: "memory");
}
__device__ __forceinline__ uint32_t mapa_sc(uint32_t la, uint32_t r) {
    uint32_t ra;
    asm("mapa.shared::cluster.u32 %0, %1, %2;" : "=r"(ra) : "r"(la), "r"(r));
    return ra;
}
__device__ __forceinline__ void st_async_b32(uint32_t raddr, uint32_t v, uint32_t rmbar) {
    asm volatile("st.async.weak.shared::cluster.mbarrier::complete_tx::bytes.b32 [%0], %1, [%2];"
                 :: "r"(raddr), "r"(v), "r"(rmbar) : "memory");
}
__device__ __forceinline__ void mbar_init(uint32_t mb, uint32_t cnt) {
    asm volatile("mbarrier.init.shared.b64 [%0], %1;" :: "r"(mb), "r"(cnt) : "memory");
}
__device__ __forceinline__ void mbar_arrive_expect(uint32_t mb, uint32_t bytes) {
    asm volatile("mbarrier.arrive.expect_tx.shared.b64 _, [%0], %1;" :: "r"(mb), "r"(bytes) : "memory");
}
__device__ __forceinline__ void mbar_wait_parity(uint32_t mb, uint32_t parity) {
    uint32_t done;
    asm volatile(
        "{\n\t.reg .pred p;\n\t"
        "mbarrier.try_wait.parity.acquire.cluster.shared::cta.b64 p, [%1], %2;\n\t"
        "selp.b32 %0, 1, 0, p;\n\t}"
        : "=r"(done) : "r"(mb), "r"(parity) : "memory");
    if (!done) {
        asm volatile(
            "{\n\t.reg .pred P1;\n\t"
            "WL_%=:\n\t"
            "mbarrier.try_wait.parity.acquire.cluster.shared::cta.b64 P1, [%0], %1, 0x989680;\n\t"
            "@P1 bra.uni WD_%=;\n\t"
            "bra.uni WL_%=;\n\t"
            "WD_%=:\n\t}"
            :: "r"(mb), "r"(parity) : "memory");
    }
}

// ---------------- GEMM: Gi[t][n] = sum_k A(t,k)*W[n][k] + bih[n] ----------------
__global__ void gemm_gi_kernel(const int* __restrict__ x,
                               const float* __restrict__ emb,
                               int mode, int K,
                               const float* __restrict__ Wf, const float* __restrict__ Wb,
                               const float* __restrict__ bf, const float* __restrict__ bb,
                               float* __restrict__ GiF_out, float* __restrict__ GiB_out)
{
    const float* W   = blockIdx.z ? Wb : Wf;
    const float* bih = blockIdx.z ? bb : bf;
    float* Gi        = blockIdx.z ? GiB_out : GiF_out;

    __shared__ float As[32][68];
    __shared__ float Bs[32][68];

    int tid = threadIdx.x;
    int ty = tid >> 4, tx = tid & 15;
    int m0 = blockIdx.x * 64, n0 = blockIdx.y * 64;

    int lr = tid >> 2;
    int kc = (tid & 3) * 8;

    const float* arow;
    if (mode == 0) arow = emb + (size_t)x[m0 + lr] * 256;
    else           arow = g_O0 + (size_t)(m0 + lr) * K;
    const float* brow = W + (size_t)(n0 + lr) * K;

    float acc[4][4] = {};

    for (int k0 = 0; k0 < K; k0 += 32) {
        float4 a0 = *(const float4*)(arow + k0 + kc);
        float4 a1 = *(const float4*)(arow + k0 + kc + 4);
        float4 b0 = *(const float4*)(brow + k0 + kc);
        float4 b1 = *(const float4*)(brow + k0 + kc + 4);
        __syncthreads();
        As[kc+0][lr]=a0.x; As[kc+1][lr]=a0.y; As[kc+2][lr]=a0.z; As[kc+3][lr]=a0.w;
        As[kc+4][lr]=a1.x; As[kc+5][lr]=a1.y; As[kc+6][lr]=a1.z; As[kc+7][lr]=a1.w;
        Bs[kc+0][lr]=b0.x; Bs[kc+1][lr]=b0.y; Bs[kc+2][lr]=b0.z; Bs[kc+3][lr]=b0.w;
        Bs[kc+4][lr]=b1.x; Bs[kc+5][lr]=b1.y; Bs[kc+6][lr]=b1.z; Bs[kc+7][lr]=b1.w;
        __syncthreads();
#pragma unroll
        for (int kk = 0; kk < 32; kk++) {
            float4 av = *(const float4*)&As[kk][ty * 4];
            float4 bv = *(const float4*)&Bs[kk][tx * 4];
            float a4[4] = {av.x, av.y, av.z, av.w};
            float b4[4] = {bv.x, bv.y, bv.z, bv.w};
#pragma unroll
            for (int i = 0; i < 4; i++)
#pragma unroll
                for (int j = 0; j < 4; j++)
                    acc[i][j] += a4[i] * b4[j];
        }
    }
#pragma unroll
    for (int i = 0; i < 4; i++) {
        int m = m0 + ty * 4 + i;
#pragma unroll
        for (int j = 0; j < 4; j++) {
            int n = n0 + tx * 4 + j;
            Gi[(size_t)m * G3 + n] = acc[i][j] + bih[n];
        }
    }
}

// ---------------- cluster GRU recurrence (one layer, both cells) ----------------
// Grid = 16 CTAs = 2 clusters of 8. CTA rank owns h[rank*32 .. rank*32+32).
// 384 threads: q=tid/96 (K-chunk of 64), rl=tid%96 (local gate row).
// mbarrier transaction sync instead of cluster.sync (no L1 flush, ~60-90cyc wakeup).
__global__ void __cluster_dims__(CLN, 1, 1) recur_kernel(
    const float* __restrict__ WhhF, const float* __restrict__ WhhB,
    const float* __restrict__ bhhF, const float* __restrict__ bhhB,
    const float* __restrict__ hinit, int slotBase, int layer)
{
    int cell = blockIdx.x / CLN;
    unsigned rank;
    asm("mov.u32 %0, %%cluster_ctarank;" : "=r"(rank));

    const float* Gi  = cell ? g_GiB : g_GiF;
    const float* Whh = cell ? WhhB : WhhF;
    const float* bhh = cell ? bhhB : bhhF;
    float* Out       = layer ? g_H1 : g_O0;

    __shared__ float hbuf[2][256];
    __shared__ float red[4 * 96];
    __shared__ float gis[96];
    __shared__ float bhhs[96];
    __shared__ __align__(8) uint64_t s_mb;

    int tid = threadIdx.x;
    int q  = tid / 96;
    int rl = tid % 96;
    int g  = rl >> 5, jj = rl & 31;
    int rowGlobal = g * 256 + (int)rank * 32 + jj;

    // preload Whh slice into registers (64 floats/thread)
    float4 w4[16];
    const float* wp = Whh + (size_t)rowGlobal * 256 + q * 64;
#pragma unroll
    for (int i = 0; i < 16; i++) w4[i] = *(const float4*)(wp + i * 4);

    uint32_t mb = (uint32_t)__cvta_generic_to_shared(&s_mb);
    if (tid == 0) mbar_init(mb, 1);
    if (tid < 256) hbuf[0][tid] = hinit[(slotBase + cell) * 256 + tid];
    if (tid < 96)  bhhs[tid] = bhh[rowGlobal];
    __syncthreads();
    cluster_sync_asm();   // one-time: peers' mbarriers + hbuf[0] ready

    // remote dest addresses for this lane's h value (computed once)
    uint32_t la_buf0 = 0, la_buf1 = 0;
    if (tid < 32) {
        la_buf0 = (uint32_t)__cvta_generic_to_shared(&hbuf[0][rank * 32 + tid]);
        la_buf1 = (uint32_t)__cvta_generic_to_shared(&hbuf[1][rank * 32 + tid]);
    }

    float gi_cur = (tid < 96) ? Gi[rowGlobal] : 0.f;

    for (int t = 0; t < LSEQ; t++) {
        int cur = t & 1;
        if (tid == 0) mbar_arrive_expect(mb, 1024);
        if (tid < 96) {
            gis[tid] = gi_cur;
            if (t + 1 < LSEQ) gi_cur = Gi[(size_t)(t + 1) * G3 + rowGlobal];  // prefetch
        }

        const float* hc = hbuf[cur] + q * 64;
        float ax = 0.f, ay = 0.f, az = 0.f, aw = 0.f;
#pragma unroll
        for (int i = 0; i < 16; i++) {
            float4 hv = *(const float4*)(hc + i * 4);
            ax += w4[i].x * hv.x; ay += w4[i].y * hv.y;
            az += w4[i].z * hv.z; aw += w4[i].w * hv.w;
        }
        red[q * 96 + rl] = (ax + ay) + (az + aw);

        if (tid < 32) {
            asm volatile("bar.sync 0, 384;" ::: "memory");
            float ghr = red[tid]      + red[96 + tid]      + red[192 + tid]      + red[288 + tid]      + bhhs[tid];
            float ghz = red[32 + tid] + red[96 + 32 + tid] + red[192 + 32 + tid] + red[288 + 32 + tid] + bhhs[32 + tid];
            float ghn = red[64 + tid] + red[96 + 64 + tid] + red[192 + 64 + tid] + red[288 + 64 + tid] + bhhs[64 + tid];
            float r = fsigm(gis[tid] + ghr);
            float z = fsigm(gis[32 + tid] + ghz);
            float n = ftanh(gis[64 + tid] + r * ghn);
            float hp = hbuf[cur][rank * 32 + tid];
            float hn_ = (1.0f - z) * n + z * hp;
            Out[(size_t)t * 512 + cell * 256 + rank * 32 + tid] = hn_;

            uint32_t la = (cur ? la_buf0 : la_buf1);   // write into hbuf[nxt]
            uint32_t hv = __float_as_uint(hn_);
#pragma unroll
            for (int d = 0; d < CLN; d++) {
                uint32_t ra = mapa_sc(la, (uint32_t)d);
                uint32_t rm = mapa_sc(mb, (uint32_t)d);
                st_async_b32(ra, hv, rm);
            }
        } else {
            asm volatile("bar.arrive 0, 384;" ::: "memory");
        }
        mbar_wait_parity(mb, (uint32_t)(t & 1));
    }
}

// ---------------- per-row log_softmax over 512: H1 -> EO ----------------
__global__ void logsoftmax_kernel()
{
    int t = blockIdx.x, tid = threadIdx.x;   // 128 threads
    __shared__ float sred[4], sred2[4];
    float4 v = *(const float4*)(g_H1 + (size_t)t * 512 + tid * 4);
    float m = fmaxf(fmaxf(v.x, v.y), fmaxf(v.z, v.w));
    m = wred_max(m);
    if ((tid & 31) == 0) sred[tid >> 5] = m;
    __syncthreads();
    m = fmaxf(fmaxf(sred[0], sred[1]), fmaxf(sred[2], sred[3]));
    float s = expf(v.x - m) + expf(v.y - m) + expf(v.z - m) + expf(v.w - m);
    s = wred_sum(s);
    if ((tid & 31) == 0) sred2[tid >> 5] = s;
    __syncthreads();
    s = sred2[0] + sred2[1] + sred2[2] + sred2[3];
    float lg = m + logf(s);
    float4 o4 = {v.x - lg, v.y - lg, v.z - lg, v.w - lg};
    *(float4*)(g_EO + (size_t)t * 512 + tid * 4) = o4;
}

// ---------------- decoder table: 6 CTAs (one per input tag), 1024 threads ----------------
__global__ void decoder_kernel(const float* __restrict__ de_emb,
                               const float* __restrict__ attn_W, const float* __restrict__ attn_b,
                               const float* __restrict__ comb_W, const float* __restrict__ comb_b,
                               const float* __restrict__ de_Wih, const float* __restrict__ de_Whh,
                               const float* __restrict__ de_bih, const float* __restrict__ de_bhh,
                               const float* __restrict__ h2t_W,  const float* __restrict__ h2t_b)
{
    int tag = blockIdx.x;
    __shared__ float s_cat[1024], s_dh[512], s_aw[1024], s_tmp[1024];
    __shared__ float s_o[512], s_gi[1536], s_gh[1536], s_hn[512];
    __shared__ float s_logit[8], s_red[32], s_bc[2];

    int tid = threadIdx.x;
    int lane = tid & 31, w = tid >> 5;

    if (tid < 512) {
        s_cat[tid] = de_emb[tag * 512 + tid];
    } else {
        int j = tid - 512;
        float v = (j < 256) ? g_O0[(size_t)(LSEQ - 1) * 512 + j]
                            : g_H1[(size_t)(LSEQ - 1) * 512 + j];
        s_dh[j] = v;
        s_cat[tid] = v;
    }
    __syncthreads();

    for (int r = 0; r < 32; r++) {
        int m = w * 32 + r;
        const float4* wr = (const float4*)(attn_W + (size_t)m * 1024);
        float acc = 0.f;
#pragma unroll
        for (int i = 0; i < 8; i++) {
            float4 wv = wr[lane + i * 32];
            float4 cv = *(const float4*)&s_cat[(lane + i * 32) * 4];
            acc += wv.x * cv.x + wv.y * cv.y + wv.z * cv.z + wv.w * cv.w;
        }
        acc = wred_sum(acc);
        if (lane == 0) s_aw[m] = acc + attn_b[m];
    }
    __syncthreads();

    {
        float v = s_aw[tid];
        float m = wred_max(v);
        if (lane == 0) s_red[w] = m;
        __syncthreads();
        if (w == 0) {
            float mm = s_red[lane];
            mm = wred_max(mm);
            if (lane == 0) s_bc[0] = mm;
        }
        __syncthreads();
        float M = s_bc[0];
        float ex = expf(v - M);
        float s = wred_sum(ex);
        if (lane == 0) s_red[w] = s;
        __syncthreads();
        if (w == 0) {
            float ss = s_red[lane];
            ss = wred_sum(ss);
            if (lane == 0) s_bc[1] = ss;
        }
        __syncthreads();
        s_aw[tid] = ex / s_bc[1];
    }
    __syncthreads();

    {
        int j = tid & 511, half = tid >> 9;
        float acc = 0.f;
        int t0 = half * 512;
#pragma unroll 8
        for (int t2 = t0; t2 < t0 + 512; t2++)
            acc += s_aw[t2] * g_EO[(size_t)t2 * 512 + j];
        s_tmp[tid] = acc;
    }
    __syncthreads();
    if (tid < 512) s_cat[512 + tid] = s_tmp[tid] + s_tmp[tid + 512];
    __syncthreads();

    for (int r = 0; r < 16; r++) {
        int m = w * 16 + r;
        const float4* wr = (const float4*)(comb_W + (size_t)m * 1024);
        float acc = 0.f;
#pragma unroll
        for (int i = 0; i < 8; i++) {
            float4 wv = wr[lane + i * 32];
            float4 cv = *(const float4*)&s_cat[(lane + i * 32) * 4];
            acc += wv.x * cv.x + wv.y * cv.y + wv.z * cv.z + wv.w * cv.w;
        }
        acc = wred_sum(acc);
        if (lane == 0) s_o[m] = fmaxf(acc + comb_b[m], 0.f);
    }
    __syncthreads();

    for (int idx = w; idx < 3072; idx += 32) {
        const float* Wrow;
        const float* xin;
        int m;
        if (idx < 1536) { m = idx;        Wrow = de_Wih + (size_t)m * 512; xin = s_o;  }
        else            { m = idx - 1536; Wrow = de_Whh + (size_t)m * 512; xin = s_dh; }
        float acc = 0.f;
#pragma unroll
        for (int i = 0; i < 4; i++) {
            float4 wv = *(const float4*)(Wrow + (size_t)(lane + i * 32) * 4);
            float4 cv = *(const float4*)&xin[(lane + i * 32) * 4];
            acc += wv.x * cv.x + wv.y * cv.y + wv.z * cv.z + wv.w * cv.w;
        }
        acc = wred_sum(acc);
        if (lane == 0) {
            if (idx < 1536) s_gi[m] = acc + de_bih[m];
            else            s_gh[m] = acc + de_bhh[m];
        }
    }
    __syncthreads();

    if (tid < 512) {
        float r = sigm(s_gi[tid] + s_gh[tid]);
        float z = sigm(s_gi[512 + tid] + s_gh[512 + tid]);
        float n = tanhf(s_gi[1024 + tid] + r * s_gh[1024 + tid]);
        s_hn[tid] = (1.0f - z) * n + z * s_dh[tid];
    }
    __syncthreads();

    if (w < NTAGS) {
        const float4* wr = (const float4*)(h2t_W + (size_t)w * 512);
        float acc = 0.f;
#pragma unroll
        for (int i = 0; i < 4; i++) {
            float4 wv = wr[lane + i * 32];
            float4 cv = *(const float4*)&s_hn[(lane + i * 32) * 4];
            acc += wv.x * cv.x + wv.y * cv.y + wv.z * cv.z + wv.w * cv.w;
        }
        acc = wred_sum(acc);
        if (lane == 0) s_logit[w] = acc + h2t_b[w];
    }
    __syncthreads();

    if (tid == 0) {
        float mx = s_logit[0];
        int am = 0;
        for (int i = 1; i < NTAGS; i++)
            if (s_logit[i] > mx) { mx = s_logit[i]; am = i; }
        float se = 0.f;
        for (int i = 0; i < NTAGS; i++) se += expf(s_logit[i] - mx);
        g_tab_val[tag]  = s_logit[0] - mx - logf(se);
        g_tab_next[tag] = am;
    }
}

// ---------------- final: simulate 6-state chain via cycle detection + fill output ----------------
__global__ void final_kernel(const float* __restrict__ h2t_W,
                             const float* __restrict__ h2t_b,
                             float* __restrict__ out)
{
    __shared__ float s_rowsum[NTAGS], s_val[NTAGS], s_b[NTAGS];
    __shared__ int   s_next[NTAGS], s_seq[8];
    __shared__ int   s_tail, s_per;

    int tid = threadIdx.x, lane = tid & 31, w = tid >> 5;
    if (w < NTAGS) {
        float acc = 0.f;
        for (int i = lane; i < 512; i += 32) acc += h2t_W[(size_t)w * 512 + i];
        acc = wred_sum(acc);
        if (lane == 0) s_rowsum[w] = acc;
    }
    if (tid < NTAGS) {
        s_val[tid]  = g_tab_val[tid];
        s_next[tid] = g_tab_next[tid];
        s_b[tid]    = h2t_b[tid];
    }
    __syncthreads();

    if (tid == 0) {
        int s = START_TAG;
        int seq[8];
        for (int i = 0; i < 8; i++) { seq[i] = s; s_seq[i] = s; s = s_next[s]; }
        int tail = 0, per = 1;
        bool found = false;
        for (int k = 1; k < 8 && !found; k++)
            for (int j = 0; j < k; j++)
                if (seq[k] == seq[j]) { tail = j; per = k - j; found = true; break; }
        s_tail = tail; s_per = per;
    }
    __syncthreads();

    int i = tid;
    int st = (i < s_tail) ? s_seq[i] : s_seq[s_tail + (i - s_tail) % s_per];
    float c = s_val[st];
#pragma unroll
    for (int t = 0; t < NTAGS; t++)
        out[(size_t)i * NTAGS + t] = c * s_rowsum[t] + s_b[t];
}

// ---------------- host ----------------
extern "C" void kernel_launch(void* const* d_in, const int* in_sizes, int n_in,
                              void* d_out, int out_size)
{
    const int*   x       = (const int*)  d_in[0];
    const float* emb     = (const float*)d_in[1];
    const float* Wih0f   = (const float*)d_in[2];
    const float* Whh0f   = (const float*)d_in[3];
    const float* bih0f   = (const float*)d_in[4];
    const float* bhh0f   = (const float*)d_in[5];
    const float* Wih0b   = (const float*)d_in[6];
    const float* Whh0b   = (const float*)d_in[7];
    const float* bih0b   = (const float*)d_in[8];
    const float* bhh0b   = (const float*)d_in[9];
    const float* Wih1f   = (const float*)d_in[10];
    const float* Whh1f   = (const float*)d_in[11];
    const float* bih1f   = (const float*)d_in[12];
    const float* bhh1f   = (const float*)d_in[13];
    const float* Wih1b   = (const float*)d_in[14];
    const float* Whh1b   = (const float*)d_in[15];
    const float* bih1b   = (const float*)d_in[16];
    const float* bhh1b   = (const float*)d_in[17];
    const float* ehid0   = (const float*)d_in[18];
    const float* de_emb  = (const float*)d_in[19];
    const float* attn_W  = (const float*)d_in[20];
    const float* attn_b  = (const float*)d_in[21];
    const float* comb_W  = (const float*)d_in[22];
    const float* comb_b  = (const float*)d_in[23];
    const float* de_Wih  = (const float*)d_in[24];
    const float* de_Whh  = (const float*)d_in[25];
    const float* de_bih  = (const float*)d_in[26];
    const float* de_bhh  = (const float*)d_in[27];
    const float* h2t_W   = (const float*)d_in[28];
    const float* h2t_b   = (const float*)d_in[29];
    float* out = (float*)d_out;

    float *GiF_p = nullptr, *GiB_p = nullptr;
    cudaGetSymbolAddress((void**)&GiF_p, g_GiF);
    cudaGetSymbolAddress((void**)&GiB_p, g_GiB);

    gemm_gi_kernel<<<dim3(16, 12, 2), 256>>>(x, emb, 0, 256,
                                             Wih0f, Wih0b, bih0f, bih0b, GiF_p, GiB_p);
    recur_kernel<<<16, 384>>>(Whh0f, Whh0b, bhh0f, bhh0b, ehid0, 0, 0);
    gemm_gi_kernel<<<dim3(16, 12, 2), 256>>>(nullptr, nullptr, 1, 512,
                                             Wih1f, Wih1b, bih1f, bih1b, GiF_p, GiB_p);
    recur_kernel<<<16, 384>>>(Whh1f, Whh1b, bhh1f, bhh1b, ehid0, 2, 1);
    logsoftmax_kernel<<<LSEQ, 128>>>();
    decoder_kernel<<<NTAGS, 1024>>>(de_emb, attn_W, attn_b, comb_W, comb_b,
                                    de_Wih, de_Whh, de_bih, de_bhh, h2t_W, h2t_b);
    final_kernel<<<1, 1024>>>(h2t_W, h2t_b, out);

    (void)in_sizes; (void)n_in; (void)out_size;
}

// round 5
// speedup vs baseline: 2.0961x; 1.5532x over previous
#include <cuda_runtime.h>
#include <cstdint>
#include <math.h>

// Problem dims
#define LSEQ   1024
#define G3     768        // 3*OUT_H
#define HID    256        // OUT_H
#define NTAGS  6
#define CLN    8          // cluster size per cell
#define START_TAG 4
#define CHUNK  128
#define NCHUNK (LSEQ / CHUNK)
#define NWORK  48         // GEMM worker CTAs
#define NRECUR 32         // 4 cells x 8 CTAs

// ---------------- scratch (device globals; no allocation) ----------------
__device__ __align__(16) float g_GiF [LSEQ * G3];
__device__ __align__(16) float g_GiB [LSEQ * G3];
__device__ __align__(16) float g_Gi1F[LSEQ * G3];
__device__ __align__(16) float g_Gi1B[LSEQ * G3];
__device__ __align__(16) float g_O0 [LSEQ * 512];
__device__ __align__(16) float g_H1 [LSEQ * 512];
__device__ __align__(16) float g_EO [LSEQ * 512];
__device__ float g_tab_val[NTAGS];
__device__ int   g_tab_next[NTAGS];
__device__ int   g_L0flag[NCHUNK];   // counts to 16 (L0 CTAs done with chunk)
__device__ int   g_Gflag [NCHUNK];   // counts to NWORK (Gi1 tiles ready)

// ---------------- helpers ----------------
__device__ __forceinline__ float wred_sum(float v) {
#pragma unroll
    for (int o = 16; o; o >>= 1) v += __shfl_xor_sync(0xffffffffu, v, o);
    return v;
}
__device__ __forceinline__ float wred_max(float v) {
#pragma unroll
    for (int o = 16; o; o >>= 1) v = fmaxf(v, __shfl_xor_sync(0xffffffffu, v, o));
    return v;
}
__device__ __forceinline__ float sigm(float x) { return 1.0f / (1.0f + expf(-x)); }
__device__ __forceinline__ float fsigm(float x) { return __fdividef(1.0f, 1.0f + __expf(-x)); }
__device__ __forceinline__ float ftanh(float x) {
    return 1.0f - __fdividef(2.0f, __expf(2.0f * x) + 1.0f);
}
__device__ __forceinline__ void cluster_sync_asm() {
    asm volatile("barrier.cluster.arrive.aligned;" ::: "memory");
    asm volatile("barrier.cluster.wait.aligned;" ::: "memory");
}
__device__ __forceinline__ uint32_t mapa_sc(uint32_t la, uint32_t r) {
    uint32_t ra;
    asm("mapa.shared::cluster.u32 %0, %1, %2;" : "=r"(ra) : "r"(la), "r"(r));
    return ra;
}
__device__ __forceinline__ void st_async_b32(uint32_t raddr, uint32_t v, uint32_t rmbar) {
    asm volatile("st.async.weak.shared::cluster.mbarrier::complete_tx::bytes.b32 [%0], %1, [%2];"
                 :: "r"(raddr), "r"(v), "r"(rmbar) : "memory");
}
__device__ __forceinline__ void mbar_init(uint32_t mb, uint32_t cnt) {
    asm volatile("mbarrier.init.shared.b64 [%0], %1;" :: "r"(mb), "r"(cnt) : "memory");
}
__device__ __forceinline__ void mbar_arrive_expect(uint32_t mb, uint32_t bytes) {
    asm volatile("mbarrier.arrive.expect_tx.shared.b64 _, [%0], %1;" :: "r"(mb), "r"(bytes) : "memory");
}
__device__ __forceinline__ void mbar_wait_parity(uint32_t mb, uint32_t parity) {
    uint32_t done;
    asm volatile(
        "{\n\t.reg .pred p;\n\t"
        "mbarrier.try_wait.parity.acquire.cluster.shared::cta.b64 p, [%1], %2;\n\t"
        "selp.b32 %0, 1, 0, p;\n\t}"
        : "=r"(done) : "r"(mb), "r"(parity) : "memory");
    if (!done) {
        asm volatile(
            "{\n\t.reg .pred P1;\n\t"
            "WL_%=:\n\t"
            "mbarrier.try_wait.parity.acquire.cluster.shared::cta.b64 P1, [%0], %1, 0x989680;\n\t"
            "@P1 bra.uni WD_%=;\n\t"
            "bra.uni WL_%=;\n\t"
            "WD_%=:\n\t}"
            :: "r"(mb), "r"(parity) : "memory");
    }
}
__device__ __forceinline__ int ld_acq_gpu(const int* p) {
    int v;
    asm volatile("ld.acquire.gpu.global.b32 %0, [%1];" : "=r"(v) : "l"(p) : "memory");
    return v;
}
__device__ __forceinline__ void membar_gpu() {
    asm volatile("membar.gl;" ::: "memory");
}

// ---------------- layer-0 input GEMM (+ flag zeroing) ----------------
__global__ void gemm_gi0_kernel(const int* __restrict__ x,
                                const float* __restrict__ emb,
                                const float* __restrict__ Wf, const float* __restrict__ Wb,
                                const float* __restrict__ bf, const float* __restrict__ bb)
{
    if (blockIdx.x == 0 && blockIdx.y == 0 && blockIdx.z == 0 && threadIdx.x < 2 * NCHUNK) {
        int i = threadIdx.x;
        if (i < NCHUNK) g_L0flag[i] = 0;
        else            g_Gflag[i - NCHUNK] = 0;
    }

    const float* W   = blockIdx.z ? Wb : Wf;
    const float* bih = blockIdx.z ? bb : bf;
    float* Gi        = blockIdx.z ? g_GiB : g_GiF;

    __shared__ __align__(16) float As[32][68];
    __shared__ __align__(16) float Bs[32][68];

    int tid = threadIdx.x;
    int ty = tid >> 4, tx = tid & 15;
    int m0 = blockIdx.x * 64, n0 = blockIdx.y * 64;

    int lr = tid >> 2;
    int kc = (tid & 3) * 8;

    const float* arow = emb + (size_t)x[m0 + lr] * 256;
    const float* brow = W + (size_t)(n0 + lr) * 256;

    float acc[4][4] = {};

    for (int k0 = 0; k0 < 256; k0 += 32) {
        float4 a0 = *(const float4*)(arow + k0 + kc);
        float4 a1 = *(const float4*)(arow + k0 + kc + 4);
        float4 b0 = *(const float4*)(brow + k0 + kc);
        float4 b1 = *(const float4*)(brow + k0 + kc + 4);
        __syncthreads();
        As[kc+0][lr]=a0.x; As[kc+1][lr]=a0.y; As[kc+2][lr]=a0.z; As[kc+3][lr]=a0.w;
        As[kc+4][lr]=a1.x; As[kc+5][lr]=a1.y; As[kc+6][lr]=a1.z; As[kc+7][lr]=a1.w;
        Bs[kc+0][lr]=b0.x; Bs[kc+1][lr]=b0.y; Bs[kc+2][lr]=b0.z; Bs[kc+3][lr]=b0.w;
        Bs[kc+4][lr]=b1.x; Bs[kc+5][lr]=b1.y; Bs[kc+6][lr]=b1.z; Bs[kc+7][lr]=b1.w;
        __syncthreads();
#pragma unroll
        for (int kk = 0; kk < 32; kk++) {
            float4 av = *(const float4*)&As[kk][ty * 4];
            float4 bv = *(const float4*)&Bs[kk][tx * 4];
            float a4[4] = {av.x, av.y, av.z, av.w};
            float b4[4] = {bv.x, bv.y, bv.z, bv.w};
#pragma unroll
            for (int i = 0; i < 4; i++)
#pragma unroll
                for (int j = 0; j < 4; j++)
                    acc[i][j] += a4[i] * b4[j];
        }
    }
#pragma unroll
    for (int i = 0; i < 4; i++) {
        int m = m0 + ty * 4 + i;
#pragma unroll
        for (int j = 0; j < 4; j++) {
            int n = n0 + tx * 4 + j;
            Gi[(size_t)m * G3 + n] = acc[i][j] + bih[n];
        }
    }
}

// ---------------- fused pipelined recurrence ----------------
// bid 0-31: 4 clusters of 8 = cells L0f, L0b, L1f, L1b (recurrence).
// bid 32-79: 48 GEMM workers computing Gi1 = Wih1 @ O0 chunk-by-chunk.
__global__ void __cluster_dims__(CLN, 1, 1) fused_kernel(
    const float* __restrict__ Whh0f, const float* __restrict__ bhh0f,
    const float* __restrict__ Whh0b, const float* __restrict__ bhh0b,
    const float* __restrict__ Whh1f, const float* __restrict__ bhh1f,
    const float* __restrict__ Whh1b, const float* __restrict__ bhh1b,
    const float* __restrict__ Wih1f, const float* __restrict__ bih1f,
    const float* __restrict__ Wih1b, const float* __restrict__ bih1b,
    const float* __restrict__ hinit)
{
    __shared__ __align__(16) float hbuf[2][256];
    __shared__ __align__(16) float red[4 * 96];
    __shared__ __align__(16) float gis[96];
    __shared__ __align__(16) float bhhs[96];
    __shared__ __align__(16) float As[32][68];
    __shared__ __align__(16) float Bs[32][68];
    __shared__ __align__(8)  uint64_t s_mb;

    int bid = blockIdx.x;
    int tid = threadIdx.x;

    if (bid < NRECUR) {
        // ================= recurrence cell =================
        int cell = bid >> 3;          // 0=L0f 1=L0b 2=L1f 3=L1b
        int isL1 = cell >> 1;
        int col  = cell & 1;
        unsigned rank;
        asm("mov.u32 %0, %%cluster_ctarank;" : "=r"(rank));

        const float* Gi  = isL1 ? (col ? g_Gi1B : g_Gi1F) : (col ? g_GiB : g_GiF);
        const float* Whh = (cell == 0) ? Whh0f : (cell == 1) ? Whh0b : (cell == 2) ? Whh1f : Whh1b;
        const float* bhh = (cell == 0) ? bhh0f : (cell == 1) ? bhh0b : (cell == 2) ? bhh1f : bhh1b;
        float* Out       = isL1 ? g_H1 : g_O0;

        int q  = tid / 96;
        int rl = tid % 96;
        int g  = rl >> 5, jj = rl & 31;
        int rowGlobal = g * 256 + (int)rank * 32 + jj;

        float4 w4[16];
        const float* wp = Whh + (size_t)rowGlobal * 256 + q * 64;
#pragma unroll
        for (int i = 0; i < 16; i++) w4[i] = *(const float4*)(wp + i * 4);

        uint32_t mb = (uint32_t)__cvta_generic_to_shared(&s_mb);
        if (tid == 0) mbar_init(mb, 1);
        if (tid < 256) hbuf[0][tid] = hinit[cell * 256 + tid];
        if (tid < 96)  bhhs[tid] = bhh[rowGlobal];
        __syncthreads();
        cluster_sync_asm();   // one-time: peers' mbarriers + hbuf[0] ready

        uint32_t la_buf0 = 0, la_buf1 = 0;
        if (tid < 32) {
            la_buf0 = (uint32_t)__cvta_generic_to_shared(&hbuf[0][rank * 32 + tid]);
            la_buf1 = (uint32_t)__cvta_generic_to_shared(&hbuf[1][rank * 32 + tid]);
        }

        float gi_cur = 0.f;
        if (!isL1 && tid < 96) gi_cur = Gi[rowGlobal];

        for (int t = 0; t < LSEQ; t++) {
            int cur = t & 1;

            if (isL1 && (t & (CHUNK - 1)) == 0) {
                if (tid == 0) {
                    int k = t >> 7;
                    while (ld_acq_gpu(&g_Gflag[k]) < NWORK) __nanosleep(256);
                }
                __syncthreads();
                if (tid < 96) gi_cur = Gi[(size_t)t * G3 + rowGlobal];
            }

            if (tid == 0) mbar_arrive_expect(mb, 1024);
            if (tid < 96) {
                gis[tid] = gi_cur;
                bool pf = (t + 1 < LSEQ) && !(isL1 && ((t + 1) & (CHUNK - 1)) == 0);
                if (pf) gi_cur = Gi[(size_t)(t + 1) * G3 + rowGlobal];
            }

            const float* hc = hbuf[cur] + q * 64;
            float ax = 0.f, ay = 0.f, az = 0.f, aw = 0.f;
#pragma unroll
            for (int i = 0; i < 16; i++) {
                float4 hv = *(const float4*)(hc + i * 4);
                ax += w4[i].x * hv.x; ay += w4[i].y * hv.y;
                az += w4[i].z * hv.z; aw += w4[i].w * hv.w;
            }
            red[q * 96 + rl] = (ax + ay) + (az + aw);

            if (tid < 32) {
                asm volatile("bar.sync 0, 384;" ::: "memory");
                float ghr = red[tid]      + red[96 + tid]      + red[192 + tid]      + red[288 + tid]      + bhhs[tid];
                float ghz = red[32 + tid] + red[96 + 32 + tid] + red[192 + 32 + tid] + red[288 + 32 + tid] + bhhs[32 + tid];
                float ghn = red[64 + tid] + red[96 + 64 + tid] + red[192 + 64 + tid] + red[288 + 64 + tid] + bhhs[64 + tid];
                float r = fsigm(gis[tid] + ghr);
                float z = fsigm(gis[32 + tid] + ghz);
                float n = ftanh(gis[64 + tid] + r * ghn);
                float hp = hbuf[cur][rank * 32 + tid];
                float hn_ = (1.0f - z) * n + z * hp;
                Out[(size_t)t * 512 + col * 256 + rank * 32 + tid] = hn_;

                uint32_t la = (cur ? la_buf0 : la_buf1);
                uint32_t hv = __float_as_uint(hn_);
#pragma unroll
                for (int d = 0; d < CLN; d++) {
                    uint32_t ra = mapa_sc(la, (uint32_t)d);
                    uint32_t rm = mapa_sc(mb, (uint32_t)d);
                    st_async_b32(ra, hv, rm);
                }
                if (!isL1 && (t & (CHUNK - 1)) == (CHUNK - 1)) {
                    __syncwarp();
                    if (tid == 0) {
                        membar_gpu();
                        atomicAdd(&g_L0flag[t >> 7], 1);
                    }
                }
            } else {
                asm volatile("bar.arrive 0, 384;" ::: "memory");
            }
            mbar_wait_parity(mb, (uint32_t)(t & 1));
        }
    } else {
        // ================= GEMM worker: Gi1 = Wih1 @ O0 (K=512), chunked =================
        int w = bid - NRECUR;             // 0..47
        int cellb = w / 24;               // 0=f 1=b
        int r2 = w % 24;
        int mt = r2 / 12, nt = r2 % 12;
        const float* W   = cellb ? Wih1b : Wih1f;
        const float* bih = cellb ? bih1b : bih1f;
        float* Gi        = cellb ? g_Gi1B : g_Gi1F;

        int ty = tid >> 4, tx = tid & 15;
        int lr = tid >> 2;
        int kc = (tid & 3) * 8;
        bool act = tid < 256;

        for (int k = 0; k < NCHUNK; k++) {
            if (tid == 0) {
                while (ld_acq_gpu(&g_L0flag[k]) < 16) __nanosleep(256);
            }
            __syncthreads();

            int m0 = k * CHUNK + mt * 64;
            int n0 = nt * 64;
            const float* arow = g_O0 + (size_t)(m0 + (act ? lr : 0)) * 512;
            const float* brow = W + (size_t)(n0 + (act ? lr : 0)) * 512;

            float acc[4][4] = {};
            for (int k0 = 0; k0 < 512; k0 += 32) {
                float4 a0, a1, b0, b1;
                if (act) {
                    a0 = *(const float4*)(arow + k0 + kc);
                    a1 = *(const float4*)(arow + k0 + kc + 4);
                    b0 = *(const float4*)(brow + k0 + kc);
                    b1 = *(const float4*)(brow + k0 + kc + 4);
                }
                __syncthreads();
                if (act) {
                    As[kc+0][lr]=a0.x; As[kc+1][lr]=a0.y; As[kc+2][lr]=a0.z; As[kc+3][lr]=a0.w;
                    As[kc+4][lr]=a1.x; As[kc+5][lr]=a1.y; As[kc+6][lr]=a1.z; As[kc+7][lr]=a1.w;
                    Bs[kc+0][lr]=b0.x; Bs[kc+1][lr]=b0.y; Bs[kc+2][lr]=b0.z; Bs[kc+3][lr]=b0.w;
                    Bs[kc+4][lr]=b1.x; Bs[kc+5][lr]=b1.y; Bs[kc+6][lr]=b1.z; Bs[kc+7][lr]=b1.w;
                }
                __syncthreads();
                if (act) {
#pragma unroll
                    for (int kk = 0; kk < 32; kk++) {
                        float4 av = *(const float4*)&As[kk][ty * 4];
                        float4 bv = *(const float4*)&Bs[kk][tx * 4];
                        float a4[4] = {av.x, av.y, av.z, av.w};
                        float b4[4] = {bv.x, bv.y, bv.z, bv.w};
#pragma unroll
                        for (int i = 0; i < 4; i++)
#pragma unroll
                            for (int j = 0; j < 4; j++)
                                acc[i][j] += a4[i] * b4[j];
                    }
                }
            }
            if (act) {
#pragma unroll
                for (int i = 0; i < 4; i++) {
                    int m = m0 + ty * 4 + i;
#pragma unroll
                    for (int j = 0; j < 4; j++) {
                        int n = n0 + tx * 4 + j;
                        Gi[(size_t)m * G3 + n] = acc[i][j] + bih[n];
                    }
                }
            }
            __syncthreads();
            if (tid == 0) {
                membar_gpu();
                atomicAdd(&g_Gflag[k], 1);
            }
        }
    }
}

// ---------------- per-row log_softmax over 512: H1 -> EO ----------------
__global__ void logsoftmax_kernel()
{
    int t = blockIdx.x, tid = threadIdx.x;   // 128 threads
    __shared__ float sred[4], sred2[4];
    float4 v = *(const float4*)(g_H1 + (size_t)t * 512 + tid * 4);
    float m = fmaxf(fmaxf(v.x, v.y), fmaxf(v.z, v.w));
    m = wred_max(m);
    if ((tid & 31) == 0) sred[tid >> 5] = m;
    __syncthreads();
    m = fmaxf(fmaxf(sred[0], sred[1]), fmaxf(sred[2], sred[3]));
    float s = expf(v.x - m) + expf(v.y - m) + expf(v.z - m) + expf(v.w - m);
    s = wred_sum(s);
    if ((tid & 31) == 0) sred2[tid >> 5] = s;
    __syncthreads();
    s = sred2[0] + sred2[1] + sred2[2] + sred2[3];
    float lg = m + logf(s);
    float4 o4 = {v.x - lg, v.y - lg, v.z - lg, v.w - lg};
    *(float4*)(g_EO + (size_t)t * 512 + tid * 4) = o4;
}

// ---------------- decoder table: 6 CTAs (one per input tag), 1024 threads ----------------
__global__ void decoder_kernel(const float* __restrict__ de_emb,
                               const float* __restrict__ attn_W, const float* __restrict__ attn_b,
                               const float* __restrict__ comb_W, const float* __restrict__ comb_b,
                               const float* __restrict__ de_Wih, const float* __restrict__ de_Whh,
                               const float* __restrict__ de_bih, const float* __restrict__ de_bhh,
                               const float* __restrict__ h2t_W,  const float* __restrict__ h2t_b)
{
    int tag = blockIdx.x;
    __shared__ __align__(16) float s_cat[1024];
    __shared__ __align__(16) float s_dh[512];
    __shared__ __align__(16) float s_aw[1024];
    __shared__ __align__(16) float s_tmp[1024];
    __shared__ __align__(16) float s_o[512];
    __shared__ __align__(16) float s_gi[1536];
    __shared__ __align__(16) float s_gh[1536];
    __shared__ __align__(16) float s_hn[512];
    __shared__ float s_logit[8], s_red[32], s_bc[2];

    int tid = threadIdx.x;
    int lane = tid & 31, w = tid >> 5;

    if (tid < 512) {
        s_cat[tid] = de_emb[tag * 512 + tid];
    } else {
        int j = tid - 512;
        float v = (j < 256) ? g_O0[(size_t)(LSEQ - 1) * 512 + j]
                            : g_H1[(size_t)(LSEQ - 1) * 512 + j];
        s_dh[j] = v;
        s_cat[tid] = v;
    }
    __syncthreads();

    for (int r = 0; r < 32; r++) {
        int m = w * 32 + r;
        const float4* wr = (const float4*)(attn_W + (size_t)m * 1024);
        float acc = 0.f;
#pragma unroll
        for (int i = 0; i < 8; i++) {
            float4 wv = wr[lane + i * 32];
            float4 cv = *(const float4*)&s_cat[(lane + i * 32) * 4];
            acc += wv.x * cv.x + wv.y * cv.y + wv.z * cv.z + wv.w * cv.w;
        }
        acc = wred_sum(acc);
        if (lane == 0) s_aw[m] = acc + attn_b[m];
    }
    __syncthreads();

    {
        float v = s_aw[tid];
        float m = wred_max(v);
        if (lane == 0) s_red[w] = m;
        __syncthreads();
        if (w == 0) {
            float mm = s_red[lane];
            mm = wred_max(mm);
            if (lane == 0) s_bc[0] = mm;
        }
        __syncthreads();
        float M = s_bc[0];
        float ex = expf(v - M);
        float s = wred_sum(ex);
        if (lane == 0) s_red[w] = s;
        __syncthreads();
        if (w == 0) {
            float ss = s_red[lane];
            ss = wred_sum(ss);
            if (lane == 0) s_bc[1] = ss;
        }
        __syncthreads();
        s_aw[tid] = ex / s_bc[1];
    }
    __syncthreads();

    {
        int j = tid & 511, half = tid >> 9;
        float acc = 0.f;
        int t0 = half * 512;
#pragma unroll 8
        for (int t2 = t0; t2 < t0 + 512; t2++)
            acc += s_aw[t2] * g_EO[(size_t)t2 * 512 + j];
        s_tmp[tid] = acc;
    }
    __syncthreads();
    if (tid < 512) s_cat[512 + tid] = s_tmp[tid] + s_tmp[tid + 512];
    __syncthreads();

    for (int r = 0; r < 16; r++) {
        int m = w * 16 + r;
        const float4* wr = (const float4*)(comb_W + (size_t)m * 1024);
        float acc = 0.f;
#pragma unroll
        for (int i = 0; i < 8; i++) {
            float4 wv = wr[lane + i * 32];
            float4 cv = *(const float4*)&s_cat[(lane + i * 32) * 4];
            acc += wv.x * cv.x + wv.y * cv.y + wv.z * cv.z + wv.w * cv.w;
        }
        acc = wred_sum(acc);
        if (lane == 0) s_o[m] = fmaxf(acc + comb_b[m], 0.f);
    }
    __syncthreads();

    for (int idx = w; idx < 3072; idx += 32) {
        const float* Wrow;
        const float* xin;
        int m;
        if (idx < 1536) { m = idx;        Wrow = de_Wih + (size_t)m * 512; xin = s_o;  }
        else            { m = idx - 1536; Wrow = de_Whh + (size_t)m * 512; xin = s_dh; }
        float acc = 0.f;
#pragma unroll
        for (int i = 0; i < 4; i++) {
            float4 wv = *(const float4*)(Wrow + (size_t)(lane + i * 32) * 4);
            float4 cv = *(const float4*)&xin[(lane + i * 32) * 4];
            acc += wv.x * cv.x + wv.y * cv.y + wv.z * cv.z + wv.w * cv.w;
        }
        acc = wred_sum(acc);
        if (lane == 0) {
            if (idx < 1536) s_gi[m] = acc + de_bih[m];
            else            s_gh[m] = acc + de_bhh[m];
        }
    }
    __syncthreads();

    if (tid < 512) {
        float r = sigm(s_gi[tid] + s_gh[tid]);
        float z = sigm(s_gi[512 + tid] + s_gh[512 + tid]);
        float n = tanhf(s_gi[1024 + tid] + r * s_gh[1024 + tid]);
        s_hn[tid] = (1.0f - z) * n + z * s_dh[tid];
    }
    __syncthreads();

    if (w < NTAGS) {
        const float4* wr = (const float4*)(h2t_W + (size_t)w * 512);
        float acc = 0.f;
#pragma unroll
        for (int i = 0; i < 4; i++) {
            float4 wv = wr[lane + i * 32];
            float4 cv = *(const float4*)&s_hn[(lane + i * 32) * 4];
            acc += wv.x * cv.x + wv.y * cv.y + wv.z * cv.z + wv.w * cv.w;
        }
        acc = wred_sum(acc);
        if (lane == 0) s_logit[w] = acc + h2t_b[w];
    }
    __syncthreads();

    if (tid == 0) {
        float mx = s_logit[0];
        int am = 0;
        for (int i = 1; i < NTAGS; i++)
            if (s_logit[i] > mx) { mx = s_logit[i]; am = i; }
        float se = 0.f;
        for (int i = 0; i < NTAGS; i++) se += expf(s_logit[i] - mx);
        g_tab_val[tag]  = s_logit[0] - mx - logf(se);
        g_tab_next[tag] = am;
    }
}

// ---------------- final: 6-state chain via cycle detection + fill output ----------------
__global__ void final_kernel(const float* __restrict__ h2t_W,
                             const float* __restrict__ h2t_b,
                             float* __restrict__ out)
{
    __shared__ float s_rowsum[NTAGS], s_val[NTAGS], s_b[NTAGS];
    __shared__ int   s_next[NTAGS], s_seq[8];
    __shared__ int   s_tail, s_per;

    int tid = threadIdx.x, lane = tid & 31, w = tid >> 5;
    if (w < NTAGS) {
        float acc = 0.f;
        for (int i = lane; i < 512; i += 32) acc += h2t_W[(size_t)w * 512 + i];
        acc = wred_sum(acc);
        if (lane == 0) s_rowsum[w] = acc;
    }
    if (tid < NTAGS) {
        s_val[tid]  = g_tab_val[tid];
        s_next[tid] = g_tab_next[tid];
        s_b[tid]    = h2t_b[tid];
    }
    __syncthreads();

    if (tid == 0) {
        int s = START_TAG;
        int seq[8];
        for (int i = 0; i < 8; i++) { seq[i] = s; s_seq[i] = s; s = s_next[s]; }
        int tail = 0, per = 1;
        bool found = false;
        for (int k = 1; k < 8 && !found; k++)
            for (int j = 0; j < k; j++)
                if (seq[k] == seq[j]) { tail = j; per = k - j; found = true; break; }
        s_tail = tail; s_per = per;
    }
    __syncthreads();

    int i = tid;
    int st = (i < s_tail) ? s_seq[i] : s_seq[s_tail + (i - s_tail) % s_per];
    float c = s_val[st];
#pragma unroll
    for (int t = 0; t < NTAGS; t++)
        out[(size_t)i * NTAGS + t] = c * s_rowsum[t] + s_b[t];
}

// ---------------- host ----------------
extern "C" void kernel_launch(void* const* d_in, const int* in_sizes, int n_in,
                              void* d_out, int out_size)
{
    const int*   x       = (const int*)  d_in[0];
    const float* emb     = (const float*)d_in[1];
    const float* Wih0f   = (const float*)d_in[2];
    const float* Whh0f   = (const float*)d_in[3];
    const float* bih0f   = (const float*)d_in[4];
    const float* bhh0f   = (const float*)d_in[5];
    const float* Wih0b   = (const float*)d_in[6];
    const float* Whh0b   = (const float*)d_in[7];
    const float* bih0b   = (const float*)d_in[8];
    const float* bhh0b   = (const float*)d_in[9];
    const float* Wih1f   = (const float*)d_in[10];
    const float* Whh1f   = (const float*)d_in[11];
    const float* bih1f   = (const float*)d_in[12];
    const float* bhh1f   = (const float*)d_in[13];
    const float* Wih1b   = (const float*)d_in[14];
    const float* Whh1b   = (const float*)d_in[15];
    const float* bih1b   = (const float*)d_in[16];
    const float* bhh1b   = (const float*)d_in[17];
    const float* ehid0   = (const float*)d_in[18];
    const float* de_emb  = (const float*)d_in[19];
    const float* attn_W  = (const float*)d_in[20];
    const float* attn_b  = (const float*)d_in[21];
    const float* comb_W  = (const float*)d_in[22];
    const float* comb_b  = (const float*)d_in[23];
    const float* de_Wih  = (const float*)d_in[24];
    const float* de_Whh  = (const float*)d_in[25];
    const float* de_bih  = (const float*)d_in[26];
    const float* de_bhh  = (const float*)d_in[27];
    const float* h2t_W   = (const float*)d_in[28];
    const float* h2t_b   = (const float*)d_in[29];
    float* out = (float*)d_out;

    // Layer-0 input GEMM (also zeroes pipeline flags)
    gemm_gi0_kernel<<<dim3(16, 12, 2), 256>>>(x, emb, Wih0f, Wih0b, bih0f, bih0b);
    // Fused pipelined recurrence: L0 cells + L1 cells + Gi1 GEMM workers
    fused_kernel<<<NRECUR + NWORK, 384>>>(Whh0f, bhh0f, Whh0b, bhh0b,
                                          Whh1f, bhh1f, Whh1b, bhh1b,
                                          Wih1f, bih1f, Wih1b, bih1b, ehid0);
    logsoftmax_kernel<<<LSEQ, 128>>>();
    decoder_kernel<<<NTAGS, 1024>>>(de_emb, attn_W, attn_b, comb_W, comb_b,
                                    de_Wih, de_Whh, de_bih, de_bhh, h2t_W, h2t_b);
    final_kernel<<<1, 1024>>>(h2t_W, h2t_b, out);

    (void)in_sizes; (void)n_in; (void)out_size;
}

// round 6
// speedup vs baseline: 2.1948x; 1.0471x over previous
#include <cuda_runtime.h>
#include <cstdint>
#include <math.h>

// Problem dims
#define LSEQ   1024
#define G3     768        // 3*OUT_H
#define HID    256        // OUT_H
#define NTAGS  6
#define CLN    8          // cluster size per cell
#define START_TAG 4
#define CHUNK  64
#define CSHIFT 6
#define NCHUNK (LSEQ / CHUNK)
#define NWORK  24         // GEMM worker CTAs (12 n-tiles x 2 cells, 1 m-tile/chunk)
#define NRECUR 32         // 4 cells x 8 CTAs

// ---------------- scratch (device globals; no allocation) ----------------
__device__ __align__(16) float g_GiF [LSEQ * G3];
__device__ __align__(16) float g_GiB [LSEQ * G3];
__device__ __align__(16) float g_Gi1F[LSEQ * G3];
__device__ __align__(16) float g_Gi1B[LSEQ * G3];
__device__ __align__(16) float g_O0 [LSEQ * 512];
__device__ __align__(16) float g_H1 [LSEQ * 512];
__device__ __align__(16) float g_EO [LSEQ * 512];
__device__ int   g_L0flag[NCHUNK];   // counts to 16 (L0 CTAs done with chunk)
__device__ int   g_Gflag [NCHUNK];   // counts to NWORK (Gi1 tiles ready)
// decoder staging
__device__ __align__(16) float g_awl [NTAGS * 1024];
__device__ float g_Mx[NTAGS], g_Sx[NTAGS];
__device__ __align__(16) float g_ctxp[16 * NTAGS * 512];
__device__ __align__(16) float g_cat2[NTAGS * 1024];
__device__ __align__(16) float g_oo  [NTAGS * 512];
__device__ __align__(16) float g_gi  [NTAGS * 1536];
__device__ __align__(16) float g_gh  [1536];

// ---------------- helpers ----------------
__device__ __forceinline__ float wred_sum(float v) {
#pragma unroll
    for (int o = 16; o; o >>= 1) v += __shfl_xor_sync(0xffffffffu, v, o);
    return v;
}
__device__ __forceinline__ float wred_max(float v) {
#pragma unroll
    for (int o = 16; o; o >>= 1) v = fmaxf(v, __shfl_xor_sync(0xffffffffu, v, o));
    return v;
}
__device__ __forceinline__ float sigm(float x) { return 1.0f / (1.0f + expf(-x)); }
__device__ __forceinline__ float fsigm(float x) { return __fdividef(1.0f, 1.0f + __expf(-x)); }
__device__ __forceinline__ float ftanh(float x) {
    return 1.0f - __fdividef(2.0f, __expf(2.0f * x) + 1.0f);
}
__device__ __forceinline__ void cluster_sync_asm() {
    asm volatile("barrier.cluster.arrive.aligned;" ::: "memory");
    asm volatile("barrier.cluster.wait.aligned;" ::: "memory");
}
__device__ __forceinline__ uint32_t mapa_sc(uint32_t la, uint32_t r) {
    uint32_t ra;
    asm("mapa.shared::cluster.u32 %0, %1, %2;" : "=r"(ra) : "r"(la), "r"(r));
    return ra;
}
__device__ __forceinline__ void st_async_b32(uint32_t raddr, uint32_t v, uint32_t rmbar) {
    asm volatile("st.async.weak.shared::cluster.mbarrier::complete_tx::bytes.b32 [%0], %1, [%2];"
                 :: "r"(raddr), "r"(v), "r"(rmbar) : "memory");
}
__device__ __forceinline__ void mbar_init(uint32_t mb, uint32_t cnt) {
    asm volatile("mbarrier.init.shared.b64 [%0], %1;" :: "r"(mb), "r"(cnt) : "memory");
}
__device__ __forceinline__ void mbar_arrive_expect(uint32_t mb, uint32_t bytes) {
    asm volatile("mbarrier.arrive.expect_tx.shared.b64 _, [%0], %1;" :: "r"(mb), "r"(bytes) : "memory");
}
__device__ __forceinline__ void mbar_wait_parity(uint32_t mb, uint32_t parity) {
    uint32_t done;
    asm volatile(
        "{\n\t.reg .pred p;\n\t"
        "mbarrier.try_wait.parity.acquire.cluster.shared::cta.b64 p, [%1], %2;\n\t"
        "selp.b32 %0, 1, 0, p;\n\t}"
        : "=r"(done) : "r"(mb), "r"(parity) : "memory");
    if (!done) {
        asm volatile(
            "{\n\t.reg .pred P1;\n\t"
            "WL_%=:\n\t"
            "mbarrier.try_wait.parity.acquire.cluster.shared::cta.b64 P1, [%0], %1, 0x989680;\n\t"
            "@P1 bra.uni WD_%=;\n\t"
            "bra.uni WL_%=;\n\t"
            "WD_%=:\n\t}"
            :: "r"(mb), "r"(parity) : "memory");
    }
}
__device__ __forceinline__ int ld_acq_gpu(const int* p) {
    int v;
    asm volatile("ld.acquire.gpu.global.b32 %0, [%1];" : "=r"(v) : "l"(p) : "memory");
    return v;
}
__device__ __forceinline__ void membar_gpu() {
    asm volatile("membar.gl;" ::: "memory");
}

// ---------------- layer-0 input GEMM (+ flag zeroing) ----------------
__global__ void gemm_gi0_kernel(const int* __restrict__ x,
                                const float* __restrict__ emb,
                                const float* __restrict__ Wf, const float* __restrict__ Wb,
                                const float* __restrict__ bf, const float* __restrict__ bb)
{
    if (blockIdx.x == 0 && blockIdx.y == 0 && blockIdx.z == 0 && threadIdx.x < 2 * NCHUNK) {
        int i = threadIdx.x;
        if (i < NCHUNK) g_L0flag[i] = 0;
        else            g_Gflag[i - NCHUNK] = 0;
    }

    const float* W   = blockIdx.z ? Wb : Wf;
    const float* bih = blockIdx.z ? bb : bf;
    float* Gi        = blockIdx.z ? g_GiB : g_GiF;

    __shared__ __align__(16) float As[32][68];
    __shared__ __align__(16) float Bs[32][68];

    int tid = threadIdx.x;
    int ty = tid >> 4, tx = tid & 15;
    int m0 = blockIdx.x * 64, n0 = blockIdx.y * 64;

    int lr = tid >> 2;
    int kc = (tid & 3) * 8;

    const float* arow = emb + (size_t)x[m0 + lr] * 256;
    const float* brow = W + (size_t)(n0 + lr) * 256;

    float acc[4][4] = {};

    for (int k0 = 0; k0 < 256; k0 += 32) {
        float4 a0 = *(const float4*)(arow + k0 + kc);
        float4 a1 = *(const float4*)(arow + k0 + kc + 4);
        float4 b0 = *(const float4*)(brow + k0 + kc);
        float4 b1 = *(const float4*)(brow + k0 + kc + 4);
        __syncthreads();
        As[kc+0][lr]=a0.x; As[kc+1][lr]=a0.y; As[kc+2][lr]=a0.z; As[kc+3][lr]=a0.w;
        As[kc+4][lr]=a1.x; As[kc+5][lr]=a1.y; As[kc+6][lr]=a1.z; As[kc+7][lr]=a1.w;
        Bs[kc+0][lr]=b0.x; Bs[kc+1][lr]=b0.y; Bs[kc+2][lr]=b0.z; Bs[kc+3][lr]=b0.w;
        Bs[kc+4][lr]=b1.x; Bs[kc+5][lr]=b1.y; Bs[kc+6][lr]=b1.z; Bs[kc+7][lr]=b1.w;
        __syncthreads();
#pragma unroll
        for (int kk = 0; kk < 32; kk++) {
            float4 av = *(const float4*)&As[kk][ty * 4];
            float4 bv = *(const float4*)&Bs[kk][tx * 4];
            float a4[4] = {av.x, av.y, av.z, av.w};
            float b4[4] = {bv.x, bv.y, bv.z, bv.w};
#pragma unroll
            for (int i = 0; i < 4; i++)
#pragma unroll
                for (int j = 0; j < 4; j++)
                    acc[i][j] += a4[i] * b4[j];
        }
    }
#pragma unroll
    for (int i = 0; i < 4; i++) {
        int m = m0 + ty * 4 + i;
#pragma unroll
        for (int j = 0; j < 4; j++) {
            int n = n0 + tx * 4 + j;
            Gi[(size_t)m * G3 + n] = acc[i][j] + bih[n];
        }
    }
}

// ---------------- fused pipelined recurrence ----------------
// bid 0-31: 4 clusters of 8 = cells L0f, L0b, L1f, L1b (recurrence).
// bid 32-55: 24 GEMM workers computing Gi1 = Wih1 @ O0 chunk-by-chunk.
__global__ void __cluster_dims__(CLN, 1, 1) fused_kernel(
    const float* __restrict__ Whh0f, const float* __restrict__ bhh0f,
    const float* __restrict__ Whh0b, const float* __restrict__ bhh0b,
    const float* __restrict__ Whh1f, const float* __restrict__ bhh1f,
    const float* __restrict__ Whh1b, const float* __restrict__ bhh1b,
    const float* __restrict__ Wih1f, const float* __restrict__ bih1f,
    const float* __restrict__ Wih1b, const float* __restrict__ bih1b,
    const float* __restrict__ hinit)
{
    __shared__ __align__(16) float hbuf[2][256];
    __shared__ __align__(16) float red[4 * 96];
    __shared__ __align__(16) float gis[96];
    __shared__ __align__(16) float bhhs[96];
    __shared__ __align__(16) float As[32][68];
    __shared__ __align__(16) float Bs[32][68];
    __shared__ __align__(8)  uint64_t s_mb;

    int bid = blockIdx.x;
    int tid = threadIdx.x;

    if (bid < NRECUR) {
        // ================= recurrence cell =================
        int cell = bid >> 3;          // 0=L0f 1=L0b 2=L1f 3=L1b
        int isL1 = cell >> 1;
        int col  = cell & 1;
        unsigned rank;
        asm("mov.u32 %0, %%cluster_ctarank;" : "=r"(rank));

        const float* Gi  = isL1 ? (col ? g_Gi1B : g_Gi1F) : (col ? g_GiB : g_GiF);
        const float* Whh = (cell == 0) ? Whh0f : (cell == 1) ? Whh0b : (cell == 2) ? Whh1f : Whh1b;
        const float* bhh = (cell == 0) ? bhh0f : (cell == 1) ? bhh0b : (cell == 2) ? bhh1f : bhh1b;
        float* Out       = isL1 ? g_H1 : g_O0;

        int q  = tid / 96;
        int rl = tid % 96;
        int g  = rl >> 5, jj = rl & 31;
        int rowGlobal = g * 256 + (int)rank * 32 + jj;
        int w    = tid >> 5;
        int lane = tid & 31;

        float4 w4[16];
        const float* wp = Whh + (size_t)rowGlobal * 256 + q * 64;
#pragma unroll
        for (int i = 0; i < 16; i++) w4[i] = *(const float4*)(wp + i * 4);

        uint32_t mb = (uint32_t)__cvta_generic_to_shared(&s_mb);
        if (tid == 0) mbar_init(mb, 1);
        if (tid < 256) hbuf[0][tid] = hinit[cell * 256 + tid];
        if (tid < 96)  bhhs[tid] = bhh[rowGlobal];
        __syncthreads();
        cluster_sync_asm();   // one-time: peers' mbarriers + hbuf[0] ready

        // precompute remote addresses: warp w (0-7) owns destination CTA w
        uint32_t ra0 = 0, ra1 = 0, rmw = 0;
        if (w < 8) {
            uint32_t la0 = (uint32_t)__cvta_generic_to_shared(&hbuf[0][rank * 32 + lane]);
            uint32_t la1 = (uint32_t)__cvta_generic_to_shared(&hbuf[1][rank * 32 + lane]);
            ra0 = mapa_sc(la0, (uint32_t)w);
            ra1 = mapa_sc(la1, (uint32_t)w);
            rmw = mapa_sc(mb,  (uint32_t)w);
        }

        float gi_cur = 0.f;
        if (!isL1 && tid < 96) gi_cur = Gi[rowGlobal];

        for (int t = 0; t < LSEQ; t++) {
            int cur = t & 1;

            if (isL1 && (t & (CHUNK - 1)) == 0) {
                if (tid == 0) {
                    int k = t >> CSHIFT;
                    while (ld_acq_gpu(&g_Gflag[k]) < NWORK) __nanosleep(128);
                }
                __syncthreads();
                if (tid < 96) gi_cur = Gi[(size_t)t * G3 + rowGlobal];
            }

            if (tid == 0) mbar_arrive_expect(mb, 1024);
            if (tid < 96) {
                gis[tid] = gi_cur;
                bool pf = (t + 1 < LSEQ) && !(isL1 && ((t + 1) & (CHUNK - 1)) == 0);
                if (pf) gi_cur = Gi[(size_t)(t + 1) * G3 + rowGlobal];
            }

            const float* hc = hbuf[cur] + q * 64;
            float ax = 0.f, ay = 0.f, az = 0.f, aw = 0.f;
#pragma unroll
            for (int i = 0; i < 16; i++) {
                float4 hv = *(const float4*)(hc + i * 4);
                ax += w4[i].x * hv.x; ay += w4[i].y * hv.y;
                az += w4[i].z * hv.z; aw += w4[i].w * hv.w;
            }
            red[q * 96 + rl] = (ax + ay) + (az + aw);

            if (w < 8) {
                asm volatile("bar.sync 0, 384;" ::: "memory");
                // every warp 0-7 redundantly computes all 32 gate outputs,
                // then sends ONE st.async to its dedicated destination CTA (= w)
                float ghr = red[lane]      + red[96 + lane]      + red[192 + lane]      + red[288 + lane]      + bhhs[lane];
                float ghz = red[32 + lane] + red[96 + 32 + lane] + red[192 + 32 + lane] + red[288 + 32 + lane] + bhhs[32 + lane];
                float ghn = red[64 + lane] + red[96 + 64 + lane] + red[192 + 64 + lane] + red[288 + 64 + lane] + bhhs[64 + lane];
                float r = fsigm(gis[lane] + ghr);
                float z = fsigm(gis[32 + lane] + ghz);
                float n = ftanh(gis[64 + lane] + r * ghn);
                float hp = hbuf[cur][rank * 32 + lane];
                float hn_ = (1.0f - z) * n + z * hp;

                st_async_b32(cur ? ra0 : ra1, __float_as_uint(hn_), rmw);

                if (w == 0) {
                    Out[(size_t)t * 512 + col * 256 + rank * 32 + lane] = hn_;
                    if (!isL1 && (t & (CHUNK - 1)) == (CHUNK - 1)) {
                        __syncwarp();
                        if (lane == 0) {
                            membar_gpu();
                            atomicAdd(&g_L0flag[t >> CSHIFT], 1);
                        }
                    }
                }
            } else {
                asm volatile("bar.arrive 0, 384;" ::: "memory");
            }
            mbar_wait_parity(mb, (uint32_t)(t & 1));
        }
    } else {
        // ================= GEMM worker: Gi1 = Wih1 @ O0 (K=512), chunked =================
        int w = bid - NRECUR;             // 0..23
        int cellb = w / 12;               // 0=f 1=b
        int nt = w % 12;
        const float* W   = cellb ? Wih1b : Wih1f;
        const float* bih = cellb ? bih1b : bih1f;
        float* Gi        = cellb ? g_Gi1B : g_Gi1F;

        int ty = tid >> 4, tx = tid & 15;
        int lr = tid >> 2;
        int kc = (tid & 3) * 8;
        bool act = tid < 256;

        for (int k = 0; k < NCHUNK; k++) {
            if (tid == 0) {
                while (ld_acq_gpu(&g_L0flag[k]) < 16) __nanosleep(128);
            }
            __syncthreads();

            int m0 = k * CHUNK;
            int n0 = nt * 64;
            const float* arow = g_O0 + (size_t)(m0 + (act ? lr : 0)) * 512;
            const float* brow = W + (size_t)(n0 + (act ? lr : 0)) * 512;

            float acc[4][4] = {};
            for (int k0 = 0; k0 < 512; k0 += 32) {
                float4 a0, a1, b0, b1;
                if (act) {
                    a0 = *(const float4*)(arow + k0 + kc);
                    a1 = *(const float4*)(arow + k0 + kc + 4);
                    b0 = *(const float4*)(brow + k0 + kc);
                    b1 = *(const float4*)(brow + k0 + kc + 4);
                }
                __syncthreads();
                if (act) {
                    As[kc+0][lr]=a0.x; As[kc+1][lr]=a0.y; As[kc+2][lr]=a0.z; As[kc+3][lr]=a0.w;
                    As[kc+4][lr]=a1.x; As[kc+5][lr]=a1.y; As[kc+6][lr]=a1.z; As[kc+7][lr]=a1.w;
                    Bs[kc+0][lr]=b0.x; Bs[kc+1][lr]=b0.y; Bs[kc+2][lr]=b0.z; Bs[kc+3][lr]=b0.w;
                    Bs[kc+4][lr]=b1.x; Bs[kc+5][lr]=b1.y; Bs[kc+6][lr]=b1.z; Bs[kc+7][lr]=b1.w;
                }
                __syncthreads();
                if (act) {
#pragma unroll
                    for (int kk = 0; kk < 32; kk++) {
                        float4 av = *(const float4*)&As[kk][ty * 4];
                        float4 bv = *(const float4*)&Bs[kk][tx * 4];
                        float a4[4] = {av.x, av.y, av.z, av.w};
                        float b4[4] = {bv.x, bv.y, bv.z, bv.w};
#pragma unroll
                        for (int i = 0; i < 4; i++)
#pragma unroll
                            for (int j = 0; j < 4; j++)
                                acc[i][j] += a4[i] * b4[j];
                    }
                }
            }
            if (act) {
#pragma unroll
                for (int i = 0; i < 4; i++) {
                    int m = m0 + ty * 4 + i;
#pragma unroll
                    for (int j = 0; j < 4; j++) {
                        int n = n0 + tx * 4 + j;
                        Gi[(size_t)m * G3 + n] = acc[i][j] + bih[n];
                    }
                }
            }
            __syncthreads();
            if (tid == 0) {
                membar_gpu();
                atomicAdd(&g_Gflag[k], 1);
            }
        }
    }
}

// ---------------- per-row log_softmax over 512: H1 -> EO ----------------
__global__ void logsoftmax_kernel()
{
    int t = blockIdx.x, tid = threadIdx.x;   // 128 threads
    __shared__ float sred[4], sred2[4];
    float4 v = *(const float4*)(g_H1 + (size_t)t * 512 + tid * 4);
    float m = fmaxf(fmaxf(v.x, v.y), fmaxf(v.z, v.w));
    m = wred_max(m);
    if ((tid & 31) == 0) sred[tid >> 5] = m;
    __syncthreads();
    m = fmaxf(fmaxf(sred[0], sred[1]), fmaxf(sred[2], sred[3]));
    float s = expf(v.x - m) + expf(v.y - m) + expf(v.z - m) + expf(v.w - m);
    s = wred_sum(s);
    if ((tid & 31) == 0) sred2[tid >> 5] = s;
    __syncthreads();
    s = sred2[0] + sred2[1] + sred2[2] + sred2[3];
    float lg = m + logf(s);
    float4 o4 = {v.x - lg, v.y - lg, v.z - lg, v.w - lg};
    *(float4*)(g_EO + (size_t)t * 512 + tid * 4) = o4;
}

// ================= decoder stage kernels (tag-batched, wide) =================

// K1: attn logits. grid 64 x 256 threads. Each CTA: 16 rows (2/warp), batched over 6 tags.
__global__ void dec_attn_kernel(const float* __restrict__ de_emb,
                                const float* __restrict__ attn_W,
                                const float* __restrict__ attn_b)
{
    __shared__ __align__(16) float s_cat[NTAGS][1024];
    int tid = threadIdx.x, lane = tid & 31, w = tid >> 5;

    for (int i = tid; i < NTAGS * 1024; i += 256) {
        int tag = i >> 10, j = i & 1023;
        float v;
        if (j < 512) v = de_emb[tag * 512 + j];
        else {
            int jj = j - 512;
            v = (jj < 256) ? g_O0[(size_t)(LSEQ - 1) * 512 + jj]
                           : g_H1[(size_t)(LSEQ - 1) * 512 + jj];
        }
        s_cat[tag][j] = v;
    }
    __syncthreads();

    for (int r = 0; r < 2; r++) {
        int m = blockIdx.x * 16 + w * 2 + r;
        const float4* wr = (const float4*)(attn_W + (size_t)m * 1024);
        float acc[NTAGS] = {};
#pragma unroll
        for (int i = 0; i < 8; i++) {
            float4 wv = wr[lane + i * 32];
#pragma unroll
            for (int tg = 0; tg < NTAGS; tg++) {
                float4 cv = *(const float4*)&s_cat[tg][(lane + i * 32) * 4];
                acc[tg] += wv.x * cv.x + wv.y * cv.y + wv.z * cv.z + wv.w * cv.w;
            }
        }
#pragma unroll
        for (int tg = 0; tg < NTAGS; tg++) {
            float a = wred_sum(acc[tg]);
            if (lane == 0) g_awl[tg * 1024 + m] = a + attn_b[m];
        }
    }
}

// K2: softmax max + sumexp per tag. grid 6 x 256.
__global__ void dec_softmax_kernel()
{
    int tag = blockIdx.x, tid = threadIdx.x, lane = tid & 31, w = tid >> 5;
    __shared__ float sr[8];
    float4 v = *(const float4*)(g_awl + tag * 1024 + tid * 4);
    float m = fmaxf(fmaxf(v.x, v.y), fmaxf(v.z, v.w));
    m = wred_max(m);
    if (lane == 0) sr[w] = m;
    __syncthreads();
    if (w == 0) {
        float mm = (lane < 8) ? sr[lane] : -1e30f;
        mm = wred_max(mm);
        if (lane == 0) sr[0] = mm;
    }
    __syncthreads();
    float M = sr[0];
    float s = expf(v.x - M) + expf(v.y - M) + expf(v.z - M) + expf(v.w - M);
    s = wred_sum(s);
    __syncthreads();
    if (lane == 0) sr[w] = s;
    __syncthreads();
    if (tid == 0) {
        float ss = 0.f;
        for (int i = 0; i < 8; i++) ss += sr[i];
        g_Mx[tag] = M;
        g_Sx[tag] = ss;
    }
}

// K3: ctx partials. grid 16 (t-splits of 64) x 256. partial[tsplit][tag][j] over t-range.
__global__ void dec_ctx_kernel()
{
    __shared__ float p6[NTAGS][CHUNK];   // 6 x 64
    int ts = blockIdx.x, tid = threadIdx.x;
    int t0 = ts * 64;
    for (int i = tid; i < NTAGS * 64; i += 256) {
        int tag = i >> 6, tt = i & 63;
        p6[tag][tt] = expf(g_awl[tag * 1024 + t0 + tt] - g_Mx[tag]) / g_Sx[tag];
    }
    __syncthreads();

    int j0 = tid * 2;
    float acc[NTAGS][2] = {};
    for (int tt = 0; tt < 64; tt++) {
        float2 e = *(const float2*)(g_EO + (size_t)(t0 + tt) * 512 + j0);
#pragma unroll
        for (int tg = 0; tg < NTAGS; tg++) {
            float p = p6[tg][tt];
            acc[tg][0] += p * e.x;
            acc[tg][1] += p * e.y;
        }
    }
#pragma unroll
    for (int tg = 0; tg < NTAGS; tg++) {
        g_ctxp[(ts * NTAGS + tg) * 512 + j0]     = acc[tg][0];
        g_ctxp[(ts * NTAGS + tg) * 512 + j0 + 1] = acc[tg][1];
    }
}

// K4: assemble cat2 = [e, ctx]. grid 6 x 256.
__global__ void dec_cat2_kernel(const float* __restrict__ de_emb)
{
    int tag = blockIdx.x, tid = threadIdx.x;
    for (int j = tid; j < 512; j += 256) g_cat2[tag * 1024 + j] = de_emb[tag * 512 + j];
    for (int j = tid; j < 512; j += 256) {
        float s = 0.f;
#pragma unroll
        for (int ts = 0; ts < 16; ts++) s += g_ctxp[(ts * NTAGS + tag) * 512 + j];
        g_cat2[tag * 1024 + 512 + j] = s;
    }
}

// K5: o = relu(comb_W @ cat2 + b). grid 32 x 256, 16 rows/CTA, batched tags.
__global__ void dec_comb_kernel(const float* __restrict__ comb_W,
                                const float* __restrict__ comb_b)
{
    __shared__ __align__(16) float s_cat[NTAGS][1024];
    int tid = threadIdx.x, lane = tid & 31, w = tid >> 5;
    for (int i = tid; i < NTAGS * 1024; i += 256) s_cat[i >> 10][i & 1023] = g_cat2[i];
    __syncthreads();

    for (int r = 0; r < 2; r++) {
        int m = blockIdx.x * 16 + w * 2 + r;
        const float4* wr = (const float4*)(comb_W + (size_t)m * 1024);
        float acc[NTAGS] = {};
#pragma unroll
        for (int i = 0; i < 8; i++) {
            float4 wv = wr[lane + i * 32];
#pragma unroll
            for (int tg = 0; tg < NTAGS; tg++) {
                float4 cv = *(const float4*)&s_cat[tg][(lane + i * 32) * 4];
                acc[tg] += wv.x * cv.x + wv.y * cv.y + wv.z * cv.z + wv.w * cv.w;
            }
        }
#pragma unroll
        for (int tg = 0; tg < NTAGS; tg++) {
            float a = wred_sum(acc[tg]);
            if (lane == 0) g_oo[tg * 512 + m] = fmaxf(a + comb_b[m], 0.f);
        }
    }
}

// K6: GRU gate pre-activations. gh (tag-independent, 1536 rows) + gi (batched, 1536 rows).
// grid 96 x 256: 768 warps x 4 jobs = 3072 jobs.
__global__ void dec_gates_kernel(const float* __restrict__ de_Wih,
                                 const float* __restrict__ de_Whh,
                                 const float* __restrict__ de_bih,
                                 const float* __restrict__ de_bhh)
{
    __shared__ __align__(16) float s_o[NTAGS][512];
    __shared__ __align__(16) float s_dh[512];
    int tid = threadIdx.x, lane = tid & 31, w = tid >> 5;
    for (int i = tid; i < NTAGS * 512; i += 256) s_o[i >> 9][i & 511] = g_oo[i];
    for (int i = tid; i < 512; i += 256)
        s_dh[i] = (i < 256) ? g_O0[(size_t)(LSEQ - 1) * 512 + i]
                            : g_H1[(size_t)(LSEQ - 1) * 512 + i];
    __syncthreads();

    int wg = blockIdx.x * 8 + w;   // 0..767
    for (int r = 0; r < 4; r++) {
        int job = wg * 4 + r;      // 0..3071
        if (job < 1536) {
            // gh row
            const float4* wr = (const float4*)(de_Whh + (size_t)job * 512);
            float acc = 0.f;
#pragma unroll
            for (int i = 0; i < 4; i++) {
                float4 wv = wr[lane + i * 32];
                float4 cv = *(const float4*)&s_dh[(lane + i * 32) * 4];
                acc += wv.x * cv.x + wv.y * cv.y + wv.z * cv.z + wv.w * cv.w;
            }
            acc = wred_sum(acc);
            if (lane == 0) g_gh[job] = acc + de_bhh[job];
        } else {
            int m = job - 1536;
            const float4* wr = (const float4*)(de_Wih + (size_t)m * 512);
            float acc[NTAGS] = {};
#pragma unroll
            for (int i = 0; i < 4; i++) {
                float4 wv = wr[lane + i * 32];
#pragma unroll
                for (int tg = 0; tg < NTAGS; tg++) {
                    float4 cv = *(const float4*)&s_o[tg][(lane + i * 32) * 4];
                    acc[tg] += wv.x * cv.x + wv.y * cv.y + wv.z * cv.z + wv.w * cv.w;
                }
            }
#pragma unroll
            for (int tg = 0; tg < NTAGS; tg++) {
                float a = wred_sum(acc[tg]);
                if (lane == 0) g_gi[tg * 1536 + m] = a + de_bih[m];
            }
        }
    }
}

// K7: hn + logits + table + chain + output fill. grid 1 x 1024.
__global__ void dec_final_kernel(const float* __restrict__ h2t_W,
                                 const float* __restrict__ h2t_b,
                                 float* __restrict__ out)
{
    __shared__ __align__(16) float s_hn[NTAGS][512];
    __shared__ __align__(16) float s_dh[512];
    __shared__ float s_lg[NTAGS][NTAGS];
    __shared__ float s_rowsum[NTAGS], s_val[NTAGS], s_b[NTAGS];
    __shared__ int   s_seq[8];
    __shared__ int   s_tail, s_per;

    int tid = threadIdx.x, lane = tid & 31, w = tid >> 5;

    if (tid < 512)
        s_dh[tid] = (tid < 256) ? g_O0[(size_t)(LSEQ - 1) * 512 + tid]
                                : g_H1[(size_t)(LSEQ - 1) * 512 + tid];
    __syncthreads();

    for (int idx = tid; idx < NTAGS * 512; idx += 1024) {
        int tag = idx >> 9, j = idx & 511;
        float gir = g_gi[tag * 1536 + j],        ghr = g_gh[j];
        float giz = g_gi[tag * 1536 + 512 + j],  ghz = g_gh[512 + j];
        float gin = g_gi[tag * 1536 + 1024 + j], ghn = g_gh[1024 + j];
        float r = sigm(gir + ghr);
        float z = sigm(giz + ghz);
        float n = tanhf(gin + r * ghn);
        s_hn[tag][j] = (1.0f - z) * n + z * s_dh[j];
    }
    __syncthreads();

    // 36 logit jobs + 6 rowsum jobs over 32 warps
    for (int job = w; job < 42; job += 32) {
        if (job < 36) {
            int tag = job / NTAGS, k = job % NTAGS;
            const float4* wr = (const float4*)(h2t_W + (size_t)k * 512);
            float acc = 0.f;
#pragma unroll
            for (int i = 0; i < 4; i++) {
                float4 wv = wr[lane + i * 32];
                float4 cv = *(const float4*)&s_hn[tag][(lane + i * 32) * 4];
                acc += wv.x * cv.x + wv.y * cv.y + wv.z * cv.z + wv.w * cv.w;
            }
            acc = wred_sum(acc);
            if (lane == 0) s_lg[tag][k] = acc + h2t_b[k];
        } else {
            int k = job - 36;
            float acc = 0.f;
            for (int i = lane; i < 512; i += 32) acc += h2t_W[(size_t)k * 512 + i];
            acc = wred_sum(acc);
            if (lane == 0) { s_rowsum[k] = acc; s_b[k] = h2t_b[k]; }
        }
    }
    __syncthreads();

    if (tid == 0) {
        int nxt[NTAGS];
        for (int tg = 0; tg < NTAGS; tg++) {
            float mx = s_lg[tg][0]; int am = 0;
            for (int i = 1; i < NTAGS; i++)
                if (s_lg[tg][i] > mx) { mx = s_lg[tg][i]; am = i; }
            float se = 0.f;
            for (int i = 0; i < NTAGS; i++) se += expf(s_lg[tg][i] - mx);
            s_val[tg] = s_lg[tg][0] - mx - logf(se);
            nxt[tg] = am;
        }
        int s = START_TAG;
        int seq[8];
        for (int i = 0; i < 8; i++) { seq[i] = s; s_seq[i] = s; s = nxt[s]; }
        int tail = 0, per = 1;
        bool found = false;
        for (int k = 1; k < 8 && !found; k++)
            for (int j = 0; j < k; j++)
                if (seq[k] == seq[j]) { tail = j; per = k - j; found = true; break; }
        s_tail = tail; s_per = per;
    }
    __syncthreads();

    int i = tid;
    int st = (i < s_tail) ? s_seq[i] : s_seq[s_tail + (i - s_tail) % s_per];
    float c = s_val[st];
#pragma unroll
    for (int t = 0; t < NTAGS; t++)
        out[(size_t)i * NTAGS + t] = c * s_rowsum[t] + s_b[t];
}

// ---------------- host ----------------
extern "C" void kernel_launch(void* const* d_in, const int* in_sizes, int n_in,
                              void* d_out, int out_size)
{
    const int*   x       = (const int*)  d_in[0];
    const float* emb     = (const float*)d_in[1];
    const float* Wih0f   = (const float*)d_in[2];
    const float* Whh0f   = (const float*)d_in[3];
    const float* bih0f   = (const float*)d_in[4];
    const float* bhh0f   = (const float*)d_in[5];
    const float* Wih0b   = (const float*)d_in[6];
    const float* Whh0b   = (const float*)d_in[7];
    const float* bih0b   = (const float*)d_in[8];
    const float* bhh0b   = (const float*)d_in[9];
    const float* Wih1f   = (const float*)d_in[10];
    const float* Whh1f   = (const float*)d_in[11];
    const float* bih1f   = (const float*)d_in[12];
    const float* bhh1f   = (const float*)d_in[13];
    const float* Wih1b   = (const float*)d_in[14];
    const float* Whh1b   = (const float*)d_in[15];
    const float* bih1b   = (const float*)d_in[16];
    const float* bhh1b   = (const float*)d_in[17];
    const float* ehid0   = (const float*)d_in[18];
    const float* de_emb  = (const float*)d_in[19];
    const float* attn_W  = (const float*)d_in[20];
    const float* attn_b  = (const float*)d_in[21];
    const float* comb_W  = (const float*)d_in[22];
    const float* comb_b  = (const float*)d_in[23];
    const float* de_Wih  = (const float*)d_in[24];
    const float* de_Whh  = (const float*)d_in[25];
    const float* de_bih  = (const float*)d_in[26];
    const float* de_bhh  = (const float*)d_in[27];
    const float* h2t_W   = (const float*)d_in[28];
    const float* h2t_b   = (const float*)d_in[29];
    float* out = (float*)d_out;

    gemm_gi0_kernel<<<dim3(16, 12, 2), 256>>>(x, emb, Wih0f, Wih0b, bih0f, bih0b);
    fused_kernel<<<NRECUR + NWORK, 384>>>(Whh0f, bhh0f, Whh0b, bhh0b,
                                          Whh1f, bhh1f, Whh1b, bhh1b,
                                          Wih1f, bih1f, Wih1b, bih1b, ehid0);
    logsoftmax_kernel<<<LSEQ, 128>>>();
    dec_attn_kernel<<<64, 256>>>(de_emb, attn_W, attn_b);
    dec_softmax_kernel<<<NTAGS, 256>>>();
    dec_ctx_kernel<<<16, 256>>>();
    dec_cat2_kernel<<<NTAGS, 256>>>(de_emb);
    dec_comb_kernel<<<32, 256>>>(comb_W, comb_b);
    dec_gates_kernel<<<96, 256>>>(de_Wih, de_Whh, de_bih, de_bhh);
    dec_final_kernel<<<1, 1024>>>(h2t_W, h2t_b, out);

    (void)in_sizes; (void)n_in; (void)out_size;
}

// round 7
// speedup vs baseline: 2.3584x; 1.0746x over previous
#include <cuda_runtime.h>
#include <cstdint>
#include <math.h>

// Problem dims
#define LSEQ   1024
#define G3     768        // 3*OUT_H
#define HID    256        // OUT_H
#define NTAGS  6
#define CLN    16         // cluster size per cell
#define START_TAG 4
#define CHUNK  64
#define CSHIFT 6
#define NCHUNK (LSEQ / CHUNK)
#define NWORK  24         // GEMM worker CTAs
#define NRECUR 64         // 4 cells x 16 CTAs
#define GRID_TOTAL 96     // padded to multiple of CLN

// ---------------- scratch (device globals; no allocation) ----------------
__device__ __align__(16) float g_GiF [LSEQ * G3];
__device__ __align__(16) float g_GiB [LSEQ * G3];
__device__ __align__(16) float g_Gi1F[LSEQ * G3];
__device__ __align__(16) float g_Gi1B[LSEQ * G3];
__device__ __align__(16) float g_O0 [LSEQ * 512];
__device__ __align__(16) float g_H1 [LSEQ * 512];
__device__ __align__(16) float g_EO [LSEQ * 512];
__device__ int   g_L0flag[NCHUNK];   // counts to 32 (L0 CTAs done with chunk)
__device__ int   g_Gflag [NCHUNK];   // counts to NWORK (Gi1 tiles ready)
// decoder staging
__device__ __align__(16) float g_awl [NTAGS * 1024];
__device__ float g_Mx[NTAGS], g_Sx[NTAGS];
__device__ __align__(16) float g_ctxp[16 * NTAGS * 512];
__device__ __align__(16) float g_cat2[NTAGS * 1024];
__device__ __align__(16) float g_oo  [NTAGS * 512];
__device__ __align__(16) float g_gi  [NTAGS * 1536];
__device__ __align__(16) float g_gh  [1536];

// ---------------- helpers ----------------
__device__ __forceinline__ float wred_sum(float v) {
#pragma unroll
    for (int o = 16; o; o >>= 1) v += __shfl_xor_sync(0xffffffffu, v, o);
    return v;
}
__device__ __forceinline__ float wred_max(float v) {
#pragma unroll
    for (int o = 16; o; o >>= 1) v = fmaxf(v, __shfl_xor_sync(0xffffffffu, v, o));
    return v;
}
__device__ __forceinline__ float sigm(float x) { return 1.0f / (1.0f + expf(-x)); }
__device__ __forceinline__ float fsigm(float x) { return __fdividef(1.0f, 1.0f + __expf(-x)); }
__device__ __forceinline__ float ftanh(float x) {
    return 1.0f - __fdividef(2.0f, __expf(2.0f * x) + 1.0f);
}
__device__ __forceinline__ void cluster_sync_asm() {
    asm volatile("barrier.cluster.arrive.aligned;" ::: "memory");
    asm volatile("barrier.cluster.wait.aligned;" ::: "memory");
}
__device__ __forceinline__ uint32_t mapa_sc(uint32_t la, uint32_t r) {
    uint32_t ra;
    asm("mapa.shared::cluster.u32 %0, %1, %2;" : "=r"(ra) : "r"(la), "r"(r));
    return ra;
}
__device__ __forceinline__ void st_async_b32(uint32_t raddr, uint32_t v, uint32_t rmbar) {
    asm volatile("st.async.weak.shared::cluster.mbarrier::complete_tx::bytes.b32 [%0], %1, [%2];"
                 :: "r"(raddr), "r"(v), "r"(rmbar) : "memory");
}
__device__ __forceinline__ void mbar_init(uint32_t mb, uint32_t cnt) {
    asm volatile("mbarrier.init.shared.b64 [%0], %1;" :: "r"(mb), "r"(cnt) : "memory");
}
__device__ __forceinline__ void mbar_arrive_expect(uint32_t mb, uint32_t bytes) {
    asm volatile("mbarrier.arrive.expect_tx.shared.b64 _, [%0], %1;" :: "r"(mb), "r"(bytes) : "memory");
}
__device__ __forceinline__ void mbar_wait_parity(uint32_t mb, uint32_t parity) {
    uint32_t done;
    asm volatile(
        "{\n\t.reg .pred p;\n\t"
        "mbarrier.try_wait.parity.acquire.cluster.shared::cta.b64 p, [%1], %2;\n\t"
        "selp.b32 %0, 1, 0, p;\n\t}"
        : "=r"(done) : "r"(mb), "r"(parity) : "memory");
    if (!done) {
        asm volatile(
            "{\n\t.reg .pred P1;\n\t"
            "WL_%=:\n\t"
            "mbarrier.try_wait.parity.acquire.cluster.shared::cta.b64 P1, [%0], %1, 0x989680;\n\t"
            "@P1 bra.uni WD_%=;\n\t"
            "bra.uni WL_%=;\n\t"
            "WD_%=:\n\t}"
            :: "r"(mb), "r"(parity) : "memory");
    }
}
__device__ __forceinline__ int ld_acq_gpu(const int* p) {
    int v;
    asm volatile("ld.acquire.gpu.global.b32 %0, [%1];" : "=r"(v) : "l"(p) : "memory");
    return v;
}
__device__ __forceinline__ void membar_gpu() {
    asm volatile("membar.gl;" ::: "memory");
}

// ---------------- layer-0 input GEMM (+ flag zeroing) ----------------
__global__ void gemm_gi0_kernel(const int* __restrict__ x,
                                const float* __restrict__ emb,
                                const float* __restrict__ Wf, const float* __restrict__ Wb,
                                const float* __restrict__ bf, const float* __restrict__ bb)
{
    if (blockIdx.x == 0 && blockIdx.y == 0 && blockIdx.z == 0 && threadIdx.x < 2 * NCHUNK) {
        int i = threadIdx.x;
        if (i < NCHUNK) g_L0flag[i] = 0;
        else            g_Gflag[i - NCHUNK] = 0;
    }

    const float* W   = blockIdx.z ? Wb : Wf;
    const float* bih = blockIdx.z ? bb : bf;
    float* Gi        = blockIdx.z ? g_GiB : g_GiF;

    __shared__ __align__(16) float As[32][68];
    __shared__ __align__(16) float Bs[32][68];

    int tid = threadIdx.x;
    int ty = tid >> 4, tx = tid & 15;
    int m0 = blockIdx.x * 64, n0 = blockIdx.y * 64;

    int lr = tid >> 2;
    int kc = (tid & 3) * 8;

    const float* arow = emb + (size_t)x[m0 + lr] * 256;
    const float* brow = W + (size_t)(n0 + lr) * 256;

    float acc[4][4] = {};

    for (int k0 = 0; k0 < 256; k0 += 32) {
        float4 a0 = *(const float4*)(arow + k0 + kc);
        float4 a1 = *(const float4*)(arow + k0 + kc + 4);
        float4 b0 = *(const float4*)(brow + k0 + kc);
        float4 b1 = *(const float4*)(brow + k0 + kc + 4);
        __syncthreads();
        As[kc+0][lr]=a0.x; As[kc+1][lr]=a0.y; As[kc+2][lr]=a0.z; As[kc+3][lr]=a0.w;
        As[kc+4][lr]=a1.x; As[kc+5][lr]=a1.y; As[kc+6][lr]=a1.z; As[kc+7][lr]=a1.w;
        Bs[kc+0][lr]=b0.x; Bs[kc+1][lr]=b0.y; Bs[kc+2][lr]=b0.z; Bs[kc+3][lr]=b0.w;
        Bs[kc+4][lr]=b1.x; Bs[kc+5][lr]=b1.y; Bs[kc+6][lr]=b1.z; Bs[kc+7][lr]=b1.w;
        __syncthreads();
#pragma unroll
        for (int kk = 0; kk < 32; kk++) {
            float4 av = *(const float4*)&As[kk][ty * 4];
            float4 bv = *(const float4*)&Bs[kk][tx * 4];
            float a4[4] = {av.x, av.y, av.z, av.w};
            float b4[4] = {bv.x, bv.y, bv.z, bv.w};
#pragma unroll
            for (int i = 0; i < 4; i++)
#pragma unroll
                for (int j = 0; j < 4; j++)
                    acc[i][j] += a4[i] * b4[j];
        }
    }
#pragma unroll
    for (int i = 0; i < 4; i++) {
        int m = m0 + ty * 4 + i;
#pragma unroll
        for (int j = 0; j < 4; j++) {
            int n = n0 + tx * 4 + j;
            Gi[(size_t)m * G3 + n] = acc[i][j] + bih[n];
        }
    }
}

// ---------------- fused pipelined recurrence (cluster 16) ----------------
// bid 0-63: 4 clusters of 16 = cells L0f, L0b, L1f, L1b.
// bid 64-87: 24 GEMM workers (Gi1 = Wih1 @ O0, chunked). bid 88-95: pad, exit.
__global__ void __cluster_dims__(CLN, 1, 1) fused_kernel(
    const float* __restrict__ Whh0f, const float* __restrict__ bhh0f,
    const float* __restrict__ Whh0b, const float* __restrict__ bhh0b,
    const float* __restrict__ Whh1f, const float* __restrict__ bhh1f,
    const float* __restrict__ Whh1b, const float* __restrict__ bhh1b,
    const float* __restrict__ Wih1f, const float* __restrict__ bih1f,
    const float* __restrict__ Wih1b, const float* __restrict__ bih1b,
    const float* __restrict__ hinit)
{
    __shared__ __align__(16) float hbuf[2][256];
    __shared__ __align__(16) float red[8 * 48];
    __shared__ __align__(16) float gis[48];
    __shared__ __align__(16) float bhhs[48];
    __shared__ __align__(16) float As[32][68];
    __shared__ __align__(16) float Bs[32][68];
    __shared__ __align__(8)  uint64_t s_mb;

    int bid = blockIdx.x;
    int tid = threadIdx.x;

    if (bid < NRECUR) {
        // ================= recurrence cell =================
        int cell = bid >> 4;          // 0=L0f 1=L0b 2=L1f 3=L1b
        int isL1 = cell >> 1;
        int col  = cell & 1;
        unsigned rank;
        asm("mov.u32 %0, %%cluster_ctarank;" : "=r"(rank));

        const float* Gi  = isL1 ? (col ? g_Gi1B : g_Gi1F) : (col ? g_GiB : g_GiF);
        const float* Whh = (cell == 0) ? Whh0f : (cell == 1) ? Whh0b : (cell == 2) ? Whh1f : Whh1b;
        const float* bhh = (cell == 0) ? bhh0f : (cell == 1) ? bhh0b : (cell == 2) ? bhh1f : bhh1b;
        float* Out       = isL1 ? g_H1 : g_O0;

        int q  = tid / 48;            // 0..7, K-chunk of 32
        int rl = tid % 48;            // gate row local (g*16 + jj)
        int g  = rl >> 4, jj = rl & 15;
        int rowGlobal = g * 256 + (int)rank * 16 + jj;
        int w    = tid >> 5;
        int lane = tid & 31;

        float4 w4[8];
        const float* wp = Whh + (size_t)rowGlobal * 256 + q * 32;
#pragma unroll
        for (int i = 0; i < 8; i++) w4[i] = *(const float4*)(wp + i * 4);

        uint32_t mb = (uint32_t)__cvta_generic_to_shared(&s_mb);
        if (tid == 0) mbar_init(mb, 1);
        if (tid < 256) hbuf[0][tid] = hinit[cell * 256 + tid];
        if (tid < 48)  bhhs[tid] = bhh[rowGlobal];
        __syncthreads();
        cluster_sync_asm();   // one-time: peers' mbarriers + hbuf[0] ready

        // remote addresses. warp w -> dest w; warps 8-11 also -> dest w+4.
        uint32_t ra0a = 0, ra1a = 0, rma = 0, ra0b = 0, ra1b = 0, rmb2 = 0;
        {
            uint32_t la0 = (uint32_t)__cvta_generic_to_shared(&hbuf[0][rank * 16 + lane]);
            uint32_t la1 = (uint32_t)__cvta_generic_to_shared(&hbuf[1][rank * 16 + lane]);
            ra0a = mapa_sc(la0, (uint32_t)w);
            ra1a = mapa_sc(la1, (uint32_t)w);
            rma  = mapa_sc(mb,  (uint32_t)w);
            if (w >= 8) {
                ra0b = mapa_sc(la0, (uint32_t)(w + 4));
                ra1b = mapa_sc(la1, (uint32_t)(w + 4));
                rmb2 = mapa_sc(mb,  (uint32_t)(w + 4));
            }
        }

        float gi_cur = 0.f;
        if (!isL1 && tid < 48) gi_cur = Gi[rowGlobal];

        for (int t = 0; t < LSEQ; t++) {
            int cur = t & 1;

            if (isL1 && (t & (CHUNK - 1)) == 0) {
                if (tid == 0) {
                    int k = t >> CSHIFT;
                    while (ld_acq_gpu(&g_Gflag[k]) < NWORK) __nanosleep(128);
                }
                __syncthreads();
                if (tid < 48) gi_cur = Gi[(size_t)t * G3 + rowGlobal];
            }

            if (tid == 0) mbar_arrive_expect(mb, 1024);
            if (tid < 48) {
                gis[tid] = gi_cur;
                bool pf = (t + 1 < LSEQ) && !(isL1 && ((t + 1) & (CHUNK - 1)) == 0);
                if (pf) gi_cur = Gi[(size_t)(t + 1) * G3 + rowGlobal];
            }

            const float* hc = hbuf[cur] + q * 32;
            float ax = 0.f, ay = 0.f, az = 0.f, aw = 0.f;
#pragma unroll
            for (int i = 0; i < 8; i++) {
                float4 hv = *(const float4*)(hc + i * 4);
                ax += w4[i].x * hv.x; ay += w4[i].y * hv.y;
                az += w4[i].z * hv.z; aw += w4[i].w * hv.w;
            }
            red[q * 48 + rl] = (ax + ay) + (az + aw);
            __syncthreads();

            if (lane < 16) {
                // every warp redundantly computes all 16 gate outputs,
                // sends to its dedicated destination CTA(s)
                float ghr = bhhs[lane], ghz = bhhs[16 + lane], ghn = bhhs[32 + lane];
#pragma unroll
                for (int p = 0; p < 8; p++) {
                    ghr += red[p * 48 + lane];
                    ghz += red[p * 48 + 16 + lane];
                    ghn += red[p * 48 + 32 + lane];
                }
                float r = fsigm(gis[lane] + ghr);
                float z = fsigm(gis[16 + lane] + ghz);
                float n = ftanh(gis[32 + lane] + r * ghn);
                float hp = hbuf[cur][rank * 16 + lane];
                float hn_ = (1.0f - z) * n + z * hp;
                uint32_t hv = __float_as_uint(hn_);

                st_async_b32(cur ? ra0a : ra1a, hv, rma);
                if (w >= 8) st_async_b32(cur ? ra0b : ra1b, hv, rmb2);

                if (w == 0)
                    Out[(size_t)t * 512 + col * 256 + rank * 16 + lane] = hn_;
            }
            if (w == 0 && !isL1 && (t & (CHUNK - 1)) == (CHUNK - 1)) {
                __syncwarp();
                if (lane == 0) {
                    membar_gpu();
                    atomicAdd(&g_L0flag[t >> CSHIFT], 1);
                }
            }
            mbar_wait_parity(mb, (uint32_t)(t & 1));
        }
    } else if (bid < NRECUR + NWORK) {
        // ================= GEMM worker: Gi1 = Wih1 @ O0 (K=512), chunked =================
        int w = bid - NRECUR;             // 0..23
        int cellb = w / 12;               // 0=f 1=b
        int nt = w % 12;
        const float* W   = cellb ? Wih1b : Wih1f;
        const float* bih = cellb ? bih1b : bih1f;
        float* Gi        = cellb ? g_Gi1B : g_Gi1F;

        int ty = tid >> 4, tx = tid & 15;
        int lr = tid >> 2;
        int kc = (tid & 3) * 8;
        bool act = tid < 256;

        for (int k = 0; k < NCHUNK; k++) {
            if (tid == 0) {
                while (ld_acq_gpu(&g_L0flag[k]) < 32) __nanosleep(128);
            }
            __syncthreads();

            int m0 = k * CHUNK;
            int n0 = nt * 64;
            const float* arow = g_O0 + (size_t)(m0 + (act ? lr : 0)) * 512;
            const float* brow = W + (size_t)(n0 + (act ? lr : 0)) * 512;

            float acc[4][4] = {};
            for (int k0 = 0; k0 < 512; k0 += 32) {
                float4 a0, a1, b0, b1;
                if (act) {
                    a0 = *(const float4*)(arow + k0 + kc);
                    a1 = *(const float4*)(arow + k0 + kc + 4);
                    b0 = *(const float4*)(brow + k0 + kc);
                    b1 = *(const float4*)(brow + k0 + kc + 4);
                }
                __syncthreads();
                if (act) {
                    As[kc+0][lr]=a0.x; As[kc+1][lr]=a0.y; As[kc+2][lr]=a0.z; As[kc+3][lr]=a0.w;
                    As[kc+4][lr]=a1.x; As[kc+5][lr]=a1.y; As[kc+6][lr]=a1.z; As[kc+7][lr]=a1.w;
                    Bs[kc+0][lr]=b0.x; Bs[kc+1][lr]=b0.y; Bs[kc+2][lr]=b0.z; Bs[kc+3][lr]=b0.w;
                    Bs[kc+4][lr]=b1.x; Bs[kc+5][lr]=b1.y; Bs[kc+6][lr]=b1.z; Bs[kc+7][lr]=b1.w;
                }
                __syncthreads();
                if (act) {
#pragma unroll
                    for (int kk = 0; kk < 32; kk++) {
                        float4 av = *(const float4*)&As[kk][ty * 4];
                        float4 bv = *(const float4*)&Bs[kk][tx * 4];
                        float a4[4] = {av.x, av.y, av.z, av.w};
                        float b4[4] = {bv.x, bv.y, bv.z, bv.w};
#pragma unroll
                        for (int i = 0; i < 4; i++)
#pragma unroll
                            for (int j = 0; j < 4; j++)
                                acc[i][j] += a4[i] * b4[j];
                    }
                }
            }
            if (act) {
#pragma unroll
                for (int i = 0; i < 4; i++) {
                    int m = m0 + ty * 4 + i;
#pragma unroll
                    for (int j = 0; j < 4; j++) {
                        int n = n0 + tx * 4 + j;
                        Gi[(size_t)m * G3 + n] = acc[i][j] + bih[n];
                    }
                }
            }
            __syncthreads();
            if (tid == 0) {
                membar_gpu();
                atomicAdd(&g_Gflag[k], 1);
            }
        }
    }
    // pad CTAs (bid >= 88) fall through and exit
}

// ---------------- per-row log_softmax over 512: H1 -> EO ----------------
__global__ void logsoftmax_kernel()
{
    int t = blockIdx.x, tid = threadIdx.x;   // 128 threads
    __shared__ float sred[4], sred2[4];
    float4 v = *(const float4*)(g_H1 + (size_t)t * 512 + tid * 4);
    float m = fmaxf(fmaxf(v.x, v.y), fmaxf(v.z, v.w));
    m = wred_max(m);
    if ((tid & 31) == 0) sred[tid >> 5] = m;
    __syncthreads();
    m = fmaxf(fmaxf(sred[0], sred[1]), fmaxf(sred[2], sred[3]));
    float s = expf(v.x - m) + expf(v.y - m) + expf(v.z - m) + expf(v.w - m);
    s = wred_sum(s);
    if ((tid & 31) == 0) sred2[tid >> 5] = s;
    __syncthreads();
    s = sred2[0] + sred2[1] + sred2[2] + sred2[3];
    float lg = m + logf(s);
    float4 o4 = {v.x - lg, v.y - lg, v.z - lg, v.w - lg};
    *(float4*)(g_EO + (size_t)t * 512 + tid * 4) = o4;
}

// ================= decoder stage kernels (tag-batched, wide) =================

__global__ void dec_attn_kernel(const float* __restrict__ de_emb,
                                const float* __restrict__ attn_W,
                                const float* __restrict__ attn_b)
{
    __shared__ __align__(16) float s_cat[NTAGS][1024];
    int tid = threadIdx.x, lane = tid & 31, w = tid >> 5;

    for (int i = tid; i < NTAGS * 1024; i += 256) {
        int tag = i >> 10, j = i & 1023;
        float v;
        if (j < 512) v = de_emb[tag * 512 + j];
        else {
            int jj = j - 512;
            v = (jj < 256) ? g_O0[(size_t)(LSEQ - 1) * 512 + jj]
                           : g_H1[(size_t)(LSEQ - 1) * 512 + jj];
        }
        s_cat[tag][j] = v;
    }
    __syncthreads();

    for (int r = 0; r < 2; r++) {
        int m = blockIdx.x * 16 + w * 2 + r;
        const float4* wr = (const float4*)(attn_W + (size_t)m * 1024);
        float acc[NTAGS] = {};
#pragma unroll
        for (int i = 0; i < 8; i++) {
            float4 wv = wr[lane + i * 32];
#pragma unroll
            for (int tg = 0; tg < NTAGS; tg++) {
                float4 cv = *(const float4*)&s_cat[tg][(lane + i * 32) * 4];
                acc[tg] += wv.x * cv.x + wv.y * cv.y + wv.z * cv.z + wv.w * cv.w;
            }
        }
#pragma unroll
        for (int tg = 0; tg < NTAGS; tg++) {
            float a = wred_sum(acc[tg]);
            if (lane == 0) g_awl[tg * 1024 + m] = a + attn_b[m];
        }
    }
}

__global__ void dec_softmax_kernel()
{
    int tag = blockIdx.x, tid = threadIdx.x, lane = tid & 31, w = tid >> 5;
    __shared__ float sr[8];
    float4 v = *(const float4*)(g_awl + tag * 1024 + tid * 4);
    float m = fmaxf(fmaxf(v.x, v.y), fmaxf(v.z, v.w));
    m = wred_max(m);
    if (lane == 0) sr[w] = m;
    __syncthreads();
    if (w == 0) {
        float mm = (lane < 8) ? sr[lane] : -1e30f;
        mm = wred_max(mm);
        if (lane == 0) sr[0] = mm;
    }
    __syncthreads();
    float M = sr[0];
    float s = expf(v.x - M) + expf(v.y - M) + expf(v.z - M) + expf(v.w - M);
    s = wred_sum(s);
    __syncthreads();
    if (lane == 0) sr[w] = s;
    __syncthreads();
    if (tid == 0) {
        float ss = 0.f;
        for (int i = 0; i < 8; i++) ss += sr[i];
        g_Mx[tag] = M;
        g_Sx[tag] = ss;
    }
}

__global__ void dec_ctx_kernel()
{
    __shared__ float p6[NTAGS][64];
    int ts = blockIdx.x, tid = threadIdx.x;
    int t0 = ts * 64;
    for (int i = tid; i < NTAGS * 64; i += 256) {
        int tag = i >> 6, tt = i & 63;
        p6[tag][tt] = expf(g_awl[tag * 1024 + t0 + tt] - g_Mx[tag]) / g_Sx[tag];
    }
    __syncthreads();

    int j0 = tid * 2;
    float acc[NTAGS][2] = {};
    for (int tt = 0; tt < 64; tt++) {
        float2 e = *(const float2*)(g_EO + (size_t)(t0 + tt) * 512 + j0);
#pragma unroll
        for (int tg = 0; tg < NTAGS; tg++) {
            float p = p6[tg][tt];
            acc[tg][0] += p * e.x;
            acc[tg][1] += p * e.y;
        }
    }
#pragma unroll
    for (int tg = 0; tg < NTAGS; tg++) {
        g_ctxp[(ts * NTAGS + tg) * 512 + j0]     = acc[tg][0];
        g_ctxp[(ts * NTAGS + tg) * 512 + j0 + 1] = acc[tg][1];
    }
}

__global__ void dec_cat2_kernel(const float* __restrict__ de_emb)
{
    int tag = blockIdx.x, tid = threadIdx.x;
    for (int j = tid; j < 512; j += 256) g_cat2[tag * 1024 + j] = de_emb[tag * 512 + j];
    for (int j = tid; j < 512; j += 256) {
        float s = 0.f;
#pragma unroll
        for (int ts = 0; ts < 16; ts++) s += g_ctxp[(ts * NTAGS + tag) * 512 + j];
        g_cat2[tag * 1024 + 512 + j] = s;
    }
}

__global__ void dec_comb_kernel(const float* __restrict__ comb_W,
                                const float* __restrict__ comb_b)
{
    __shared__ __align__(16) float s_cat[NTAGS][1024];
    int tid = threadIdx.x, lane = tid & 31, w = tid >> 5;
    for (int i = tid; i < NTAGS * 1024; i += 256) s_cat[i >> 10][i & 1023] = g_cat2[i];
    __syncthreads();

    for (int r = 0; r < 2; r++) {
        int m = blockIdx.x * 16 + w * 2 + r;
        const float4* wr = (const float4*)(comb_W + (size_t)m * 1024);
        float acc[NTAGS] = {};
#pragma unroll
        for (int i = 0; i < 8; i++) {
            float4 wv = wr[lane + i * 32];
#pragma unroll
            for (int tg = 0; tg < NTAGS; tg++) {
                float4 cv = *(const float4*)&s_cat[tg][(lane + i * 32) * 4];
                acc[tg] += wv.x * cv.x + wv.y * cv.y + wv.z * cv.z + wv.w * cv.w;
            }
        }
#pragma unroll
        for (int tg = 0; tg < NTAGS; tg++) {
            float a = wred_sum(acc[tg]);
            if (lane == 0) g_oo[tg * 512 + m] = fmaxf(a + comb_b[m], 0.f);
        }
    }
}

__global__ void dec_gates_kernel(const float* __restrict__ de_Wih,
                                 const float* __restrict__ de_Whh,
                                 const float* __restrict__ de_bih,
                                 const float* __restrict__ de_bhh)
{
    __shared__ __align__(16) float s_o[NTAGS][512];
    __shared__ __align__(16) float s_dh[512];
    int tid = threadIdx.x, lane = tid & 31, w = tid >> 5;
    for (int i = tid; i < NTAGS * 512; i += 256) s_o[i >> 9][i & 511] = g_oo[i];
    for (int i = tid; i < 512; i += 256)
        s_dh[i] = (i < 256) ? g_O0[(size_t)(LSEQ - 1) * 512 + i]
                            : g_H1[(size_t)(LSEQ - 1) * 512 + i];
    __syncthreads();

    int wg = blockIdx.x * 8 + w;   // 0..767
    for (int r = 0; r < 4; r++) {
        int job = wg * 4 + r;      // 0..3071
        if (job < 1536) {
            const float4* wr = (const float4*)(de_Whh + (size_t)job * 512);
            float acc = 0.f;
#pragma unroll
            for (int i = 0; i < 4; i++) {
                float4 wv = wr[lane + i * 32];
                float4 cv = *(const float4*)&s_dh[(lane + i * 32) * 4];
                acc += wv.x * cv.x + wv.y * cv.y + wv.z * cv.z + wv.w * cv.w;
            }
            acc = wred_sum(acc);
            if (lane == 0) g_gh[job] = acc + de_bhh[job];
        } else {
            int m = job - 1536;
            const float4* wr = (const float4*)(de_Wih + (size_t)m * 512);
            float acc[NTAGS] = {};
#pragma unroll
            for (int i = 0; i < 4; i++) {
                float4 wv = wr[lane + i * 32];
#pragma unroll
                for (int tg = 0; tg < NTAGS; tg++) {
                    float4 cv = *(const float4*)&s_o[tg][(lane + i * 32) * 4];
                    acc[tg] += wv.x * cv.x + wv.y * cv.y + wv.z * cv.z + wv.w * cv.w;
                }
            }
#pragma unroll
            for (int tg = 0; tg < NTAGS; tg++) {
                float a = wred_sum(acc[tg]);
                if (lane == 0) g_gi[tg * 1536 + m] = a + de_bih[m];
            }
        }
    }
}

__global__ void dec_final_kernel(const float* __restrict__ h2t_W,
                                 const float* __restrict__ h2t_b,
                                 float* __restrict__ out)
{
    __shared__ __align__(16) float s_hn[NTAGS][512];
    __shared__ __align__(16) float s_dh[512];
    __shared__ float s_lg[NTAGS][NTAGS];
    __shared__ float s_rowsum[NTAGS], s_val[NTAGS], s_b[NTAGS];
    __shared__ int   s_seq[8];
    __shared__ int   s_tail, s_per;

    int tid = threadIdx.x, lane = tid & 31, w = tid >> 5;

    if (tid < 512)
        s_dh[tid] = (tid < 256) ? g_O0[(size_t)(LSEQ - 1) * 512 + tid]
                                : g_H1[(size_t)(LSEQ - 1) * 512 + tid];
    __syncthreads();

    for (int idx = tid; idx < NTAGS * 512; idx += 1024) {
        int tag = idx >> 9, j = idx & 511;
        float gir = g_gi[tag * 1536 + j],        ghr = g_gh[j];
        float giz = g_gi[tag * 1536 + 512 + j],  ghz = g_gh[512 + j];
        float gin = g_gi[tag * 1536 + 1024 + j], ghn = g_gh[1024 + j];
        float r = sigm(gir + ghr);
        float z = sigm(giz + ghz);
        float n = tanhf(gin + r * ghn);
        s_hn[tag][j] = (1.0f - z) * n + z * s_dh[j];
    }
    __syncthreads();

    for (int job = w; job < 42; job += 32) {
        if (job < 36) {
            int tag = job / NTAGS, k = job % NTAGS;
            const float4* wr = (const float4*)(h2t_W + (size_t)k * 512);
            float acc = 0.f;
#pragma unroll
            for (int i = 0; i < 4; i++) {
                float4 wv = wr[lane + i * 32];
                float4 cv = *(const float4*)&s_hn[tag][(lane + i * 32) * 4];
                acc += wv.x * cv.x + wv.y * cv.y + wv.z * cv.z + wv.w * cv.w;
            }
            acc = wred_sum(acc);
            if (lane == 0) s_lg[tag][k] = acc + h2t_b[k];
        } else {
            int k = job - 36;
            float acc = 0.f;
            for (int i = lane; i < 512; i += 32) acc += h2t_W[(size_t)k * 512 + i];
            acc = wred_sum(acc);
            if (lane == 0) { s_rowsum[k] = acc; s_b[k] = h2t_b[k]; }
        }
    }
    __syncthreads();

    if (tid == 0) {
        int nxt[NTAGS];
        for (int tg = 0; tg < NTAGS; tg++) {
            float mx = s_lg[tg][0]; int am = 0;
            for (int i = 1; i < NTAGS; i++)
                if (s_lg[tg][i] > mx) { mx = s_lg[tg][i]; am = i; }
            float se = 0.f;
            for (int i = 0; i < NTAGS; i++) se += expf(s_lg[tg][i] - mx);
            s_val[tg] = s_lg[tg][0] - mx - logf(se);
            nxt[tg] = am;
        }
        int s = START_TAG;
        int seq[8];
        for (int i = 0; i < 8; i++) { seq[i] = s; s_seq[i] = s; s = nxt[s]; }
        int tail = 0, per = 1;
        bool found = false;
        for (int k = 1; k < 8 && !found; k++)
            for (int j = 0; j < k; j++)
                if (seq[k] == seq[j]) { tail = j; per = k - j; found = true; break; }
        s_tail = tail; s_per = per;
    }
    __syncthreads();

    int i = tid;
    int st = (i < s_tail) ? s_seq[i] : s_seq[s_tail + (i - s_tail) % s_per];
    float c = s_val[st];
#pragma unroll
    for (int t = 0; t < NTAGS; t++)
        out[(size_t)i * NTAGS + t] = c * s_rowsum[t] + s_b[t];
}

// ---------------- host ----------------
extern "C" void kernel_launch(void* const* d_in, const int* in_sizes, int n_in,
                              void* d_out, int out_size)
{
    const int*   x       = (const int*)  d_in[0];
    const float* emb     = (const float*)d_in[1];
    const float* Wih0f   = (const float*)d_in[2];
    const float* Whh0f   = (const float*)d_in[3];
    const float* bih0f   = (const float*)d_in[4];
    const float* bhh0f   = (const float*)d_in[5];
    const float* Wih0b   = (const float*)d_in[6];
    const float* Whh0b   = (const float*)d_in[7];
    const float* bih0b   = (const float*)d_in[8];
    const float* bhh0b   = (const float*)d_in[9];
    const float* Wih1f   = (const float*)d_in[10];
    const float* Whh1f   = (const float*)d_in[11];
    const float* bih1f   = (const float*)d_in[12];
    const float* bhh1f   = (const float*)d_in[13];
    const float* Wih1b   = (const float*)d_in[14];
    const float* Whh1b   = (const float*)d_in[15];
    const float* bih1b   = (const float*)d_in[16];
    const float* bhh1b   = (const float*)d_in[17];
    const float* ehid0   = (const float*)d_in[18];
    const float* de_emb  = (const float*)d_in[19];
    const float* attn_W  = (const float*)d_in[20];
    const float* attn_b  = (const float*)d_in[21];
    const float* comb_W  = (const float*)d_in[22];
    const float* comb_b  = (const float*)d_in[23];
    const float* de_Wih  = (const float*)d_in[24];
    const float* de_Whh  = (const float*)d_in[25];
    const float* de_bih  = (const float*)d_in[26];
    const float* de_bhh  = (const float*)d_in[27];
    const float* h2t_W   = (const float*)d_in[28];
    const float* h2t_b   = (const float*)d_in[29];
    float* out = (float*)d_out;

    // allow cluster size 16 (idempotent; immediate host call, not captured)
    cudaFuncSetAttribute(fused_kernel, cudaFuncAttributeNonPortableClusterSizeAllowed, 1);

    gemm_gi0_kernel<<<dim3(16, 12, 2), 256>>>(x, emb, Wih0f, Wih0b, bih0f, bih0b);
    fused_kernel<<<GRID_TOTAL, 384>>>(Whh0f, bhh0f, Whh0b, bhh0b,
                                      Whh1f, bhh1f, Whh1b, bhh1b,
                                      Wih1f, bih1f, Wih1b, bih1b, ehid0);
    logsoftmax_kernel<<<LSEQ, 128>>>();
    dec_attn_kernel<<<64, 256>>>(de_emb, attn_W, attn_b);
    dec_softmax_kernel<<<NTAGS, 256>>>();
    dec_ctx_kernel<<<16, 256>>>();
    dec_cat2_kernel<<<NTAGS, 256>>>(de_emb);
    dec_comb_kernel<<<32, 256>>>(comb_W, comb_b);
    dec_gates_kernel<<<96, 256>>>(de_Wih, de_Whh, de_bih, de_bhh);
    dec_final_kernel<<<1, 1024>>>(h2t_W, h2t_b, out);

    (void)in_sizes; (void)n_in; (void)out_size;
}